// round 8
// baseline (speedup 1.0000x reference)
#include <cuda_runtime.h>
#include <mma.h>
#include <math.h>
#include <stdint.h>

using namespace nvcuda;

#define BATCH 2
#define SEQ   2048
#define NH    16
#define DH    128
#define DM    2048
#define NQ    ((size_t)BATCH*NH*SEQ*DH)

__device__ float g_qkv[3*(size_t)BATCH*NH*SEQ*DH];
__device__ float g_attn[(size_t)BATCH*SEQ*DM];
__device__ float g_xt[(size_t)BATCH*SEQ*DM];
__device__ float g_wq[(size_t)DM*3*DM];   // W_qkv^T [6144][2048] tf32
__device__ float g_wo[(size_t)DM*DM];     // W_out^T [2048][2048] tf32

// ---------------------------------------------------------------------------
__device__ __forceinline__ uint32_t smem_u32(const void* p) {
    return (uint32_t)__cvta_generic_to_shared(p);
}
#define CP_ASYNC16(dst_u32, src_ptr) \
    asm volatile("cp.async.cg.shared.global [%0], [%1], 16;" :: "r"(dst_u32), "l"(src_ptr))
#define CP_COMMIT()   asm volatile("cp.async.commit_group;")
#define CP_WAIT(n)    asm volatile("cp.async.wait_group %0;" :: "n"(n))

// m16n8k8 tf32 mma, D += A*B
__device__ __forceinline__ void mma_tf32(float* d, const uint32_t* a, const uint32_t* b) {
    asm volatile(
        "mma.sync.aligned.m16n8k8.row.col.f32.tf32.tf32.f32 "
        "{%0,%1,%2,%3},{%4,%5,%6,%7},{%8,%9},{%0,%1,%2,%3};"
        : "+f"(d[0]), "+f"(d[1]), "+f"(d[2]), "+f"(d[3])
        : "r"(a[0]), "r"(a[1]), "r"(a[2]), "r"(a[3]), "r"(b[0]), "r"(b[1]));
}

// ldmatrix x4: 4 8x4-fp32 quadrants, lane supplies one row address
__device__ __forceinline__ void ldsm4(uint32_t* r, uint32_t addr) {
    asm volatile("ldmatrix.sync.aligned.m8n8.x4.shared.b16 {%0,%1,%2,%3}, [%4];"
        : "=r"(r[0]), "=r"(r[1]), "=r"(r[2]), "=r"(r[3]) : "r"(addr));
}

// ---------------------------------------------------------------------------
// pre-passes
// ---------------------------------------------------------------------------
__global__ void cvt_tf32_kernel(const float* __restrict__ in,
                                float* __restrict__ out, int n4)
{
    int i = blockIdx.x * blockDim.x + threadIdx.x;
    if (i < n4) {
        float4 v = ((const float4*)in)[i];
        v.x = wmma::__float_to_tf32(v.x); v.y = wmma::__float_to_tf32(v.y);
        v.z = wmma::__float_to_tf32(v.z); v.w = wmma::__float_to_tf32(v.w);
        ((float4*)out)[i] = v;
    }
}

// in [R][C] -> out [C][R], tf32-rounded
__global__ void transpose_tf32_kernel(const float* __restrict__ in,
                                      float* __restrict__ out, int R, int C)
{
    __shared__ float t[32][33];
    const int c0 = blockIdx.x * 32, r0 = blockIdx.y * 32;
    #pragma unroll
    for (int i = 0; i < 32; i += 8)
        t[threadIdx.y + i][threadIdx.x] =
            in[(size_t)(r0 + threadIdx.y + i) * C + c0 + threadIdx.x];
    __syncthreads();
    #pragma unroll
    for (int i = 0; i < 32; i += 8)
        out[(size_t)(c0 + threadIdx.y + i) * R + r0 + threadIdx.x] =
            wmma::__float_to_tf32(t[threadIdx.x][threadIdx.y + i]);
}

// ---------------------------------------------------------------------------
// TF32 GEMM, raw m16n8k8 mma + ldmatrix.x4 fragment feed.
// C[M,N] = A[M,K] @ Bt[N,K]^T + bias. 128x128 tile, BK=32, 256 thr, 8 warps 4x2.
// smem per stage: A [128 m][36] (32 used), B [128 n][36]. 3-stage cp.async ring.
// MODE 0: A=g_xt, scatter epilogue into g_qkv (tf32-rounded).
// MODE 1: A=g_attn, row-major fp32 C.
// ---------------------------------------------------------------------------
#define GP 36                           // smem pitch (floats)
#define STAGE_F  (2*128*GP)             // 9216 floats = 36864 B
#define STAGE_B  (STAGE_F*4)
#define A_BYTES  (128*GP*4)
#define CS_PITCH 132
#define GEMM_SMEM (3*STAGE_B)           // 110592 B

template<int MODE>
__global__ __launch_bounds__(256, 2)
void gemm_tf32_kernel(const float* __restrict__ Aglob, const float* __restrict__ Bt,
                      const float* __restrict__ bias, float* __restrict__ C,
                      int M, int N, int K)
{
    extern __shared__ float sm[];
    float* Cs = sm;   // epilogue reuse: 128*132 floats = 67584 B < stages

    const float* Abase = (MODE == 1) ? (const float*)g_attn : Aglob;

    const int tid  = threadIdx.x;
    const int warp = tid >> 5, lane = tid & 31;
    const int wr   = warp >> 1;          // m band: 32*wr
    const int wc   = warp & 1;           // n band: 64*wc
    const int g    = lane >> 2, tq = lane & 3;
    const int rowBlock = blockIdx.y * 128;
    const int colBlock = blockIdx.x * 128;

    // cp.async coordinates: thread -> row t>>1 (0..127), half t&1 (16 floats)
    const int ldRow  = tid >> 1;
    const int ldHalf = (tid & 1) * 16;
    const float* Asrc = Abase + (size_t)(rowBlock + ldRow) * K + ldHalf;
    const float* Bsrc = Bt + (size_t)(colBlock + ldRow) * K + ldHalf;

    const uint32_t smBase = smem_u32(sm);
    const uint32_t ldOff  = (uint32_t)((ldRow * GP + ldHalf) * 4);

    // ldmatrix lane-address offsets (within stage)
    // A quadrants: row = wr*32 + mi*16 + (lane&15), col = (lane>>4)*4
    uint32_t aOff[2];
    #pragma unroll
    for (int mi = 0; mi < 2; mi++)
        aOff[mi] = (uint32_t)(((wr * 32 + mi * 16 + (lane & 15)) * GP + (lane >> 4) * 4) * 4);
    // B pair p covers n-tiles 2p,2p+1: row = wc*64+p*16+(lane&7)+((lane>>4)<<3),
    // col = ((lane>>3)&1)*4
    uint32_t bOff[4];
    #pragma unroll
    for (int p = 0; p < 4; p++)
        bOff[p] = (uint32_t)(A_BYTES +
                  ((wc * 64 + p * 16 + (lane & 7) + ((lane >> 4) << 3)) * GP
                   + ((lane >> 3) & 1) * 4) * 4);

    float acc[2][8][4] = {};

    const int NIT = K >> 5;

    auto issue = [&](int tt, int s) {
        const int k0 = tt << 5;
        const uint32_t sb = smBase + (uint32_t)s * STAGE_B;
        #pragma unroll
        for (int i = 0; i < 4; i++)
            CP_ASYNC16(sb + ldOff + (uint32_t)(i * 16),
                       Asrc + k0 + i * 4);
        #pragma unroll
        for (int i = 0; i < 4; i++)
            CP_ASYNC16(sb + (uint32_t)A_BYTES + ldOff + (uint32_t)(i * 16),
                       Bsrc + k0 + i * 4);
        CP_COMMIT();
    };

    issue(0, 0);

    for (int t = 0; t < NIT; t++) {
        if (t + 1 < NIT) {
            issue(t + 1, (t + 1) % 3);
            CP_WAIT(1);
        } else {
            CP_WAIT(0);
        }
        __syncthreads();

        const uint32_t sb = smBase + (uint32_t)(t % 3) * STAGE_B;
        #pragma unroll
        for (int ks = 0; ks < 4; ks++) {
            const uint32_t kb = (uint32_t)(ks * 32);   // 8 floats
            uint32_t a0[4], a1[4];
            ldsm4(a0, sb + aOff[0] + kb);
            ldsm4(a1, sb + aOff[1] + kb);
            #pragma unroll
            for (int p = 0; p < 4; p++) {
                uint32_t bb[4];
                ldsm4(bb, sb + bOff[p] + kb);
                mma_tf32(acc[0][2*p  ], a0, bb);
                mma_tf32(acc[0][2*p+1], a0, bb + 2);
                mma_tf32(acc[1][2*p  ], a1, bb);
                mma_tf32(acc[1][2*p+1], a1, bb + 2);
            }
        }
    }
    __syncthreads();   // stages dead; reuse as Cs

    // stage C in smem (known raw-mma accumulator layout)
    #pragma unroll
    for (int mi = 0; mi < 2; mi++) {
        const int r_lo = wr * 32 + mi * 16 + g;
        #pragma unroll
        for (int j = 0; j < 8; j++) {
            const int col = wc * 64 + j * 8 + 2 * tq;
            *(float2*)&Cs[r_lo * CS_PITCH + col] =
                make_float2(acc[mi][j][0], acc[mi][j][1]);
            *(float2*)&Cs[(r_lo + 8) * CS_PITCH + col] =
                make_float2(acc[mi][j][2], acc[mi][j][3]);
        }
    }
    __syncthreads();

    #pragma unroll
    for (int it = 0; it < 16; it++) {
        int u = tid + it * 256;
        int row = u >> 5, c4 = (u & 31) * 4;
        float4 v = *(float4*)&Cs[row * CS_PITCH + c4];
        const int gcol = colBlock + c4;
        v.x += bias[gcol + 0]; v.y += bias[gcol + 1];
        v.z += bias[gcol + 2]; v.w += bias[gcol + 3];
        const int gr = rowBlock + row;
        if (MODE == 0) {
            v.x = wmma::__float_to_tf32(v.x); v.y = wmma::__float_to_tf32(v.y);
            v.z = wmma::__float_to_tf32(v.z); v.w = wmma::__float_to_tf32(v.w);
            const int part = gcol >> 11;
            const int c2   = gcol & 2047;
            const int h    = c2 >> 7;
            const int d0   = c2 & 127;
            const int bb   = gr >> 11;
            const int s    = gr & 2047;
            float* dst = g_qkv + (size_t)part * NQ
                       + (((size_t)(bb * NH + h) * SEQ) + s) * DH + d0;
            *(float4*)dst = v;
        } else {
            *(float4*)(C + (size_t)gr * N + gcol) = v;
        }
    }
}

// ---------------------------------------------------------------------------
// Causal flash attention v3 (round-7 proven, unchanged).
// ---------------------------------------------------------------------------
#define FP 132
#define SP 68
#define KVSTRIDE (2*8448)
#define FLASH_SMEM ((6*8448 + 64*SP + 192) * 4)

__global__ __launch_bounds__(256)
void flash_kernel()
{
    extern __shared__ float smf[];
    float* Ss   = smf + 6 * 8448;
    float* mrow = Ss + 64 * SP;
    float* lrow = mrow + 64;
    float* arow = lrow + 64;

    const int qt = blockIdx.x, h = blockIdx.y, b = blockIdx.z;
    const int bh = b * NH + h;

    const float* Qp = g_qkv + 0 * NQ + ((size_t)bh * SEQ + qt * 64) * DH;
    const float* Kp = g_qkv + 1 * NQ + (size_t)bh * SEQ * DH;
    const float* Vp = g_qkv + 2 * NQ + (size_t)bh * SEQ * DH;

    const int tid  = threadIdx.x;
    const int warp = tid >> 5, lane = tid & 31;
    const int wr = warp >> 1, wc = warp & 1;
    const int g  = lane >> 2, tq = lane & 3;
    const int sr = wr * 16;

    const float scale = 0.08838834764831845f;

    auto issueKV = [&](int kt, int s) {
        const float* Kt = Kp + (size_t)kt * 64 * DH;
        const float* Vt = Vp + (size_t)kt * 64 * DH;
        float* Kd = smf + s * KVSTRIDE;
        float* Vd = Kd + 8448;
        #pragma unroll
        for (int it = 0; it < 8; it++) {
            int u = tid + it * 256;
            int r = u >> 5, c = (u & 31) * 4;
            CP_ASYNC16(smem_u32(&Kd[r * FP + c]), Kt + r * DH + c);
            CP_ASYNC16(smem_u32(&Vd[r * FP + c]), Vt + r * DH + c);
        }
        CP_COMMIT();
    };

    issueKV(0, 0);
    {
        float* Qtmp = smf + 2 * KVSTRIDE + 8448;
        #pragma unroll
        for (int it = 0; it < 8; it++) {
            int u = tid + it * 256;
            int r = u >> 5, c = (u & 31) * 4;
            *(float4*)&Qtmp[r * FP + c] = *(const float4*)(Qp + r * DH + c);
        }
    }
    if (tid < 64) { mrow[tid] = -1e30f; lrow[tid] = 0.f; }
    __syncthreads();

    uint32_t qf[16][4];
    {
        const float* Qtmp = smf + 2 * KVSTRIDE + 8448;
        #pragma unroll
        for (int ks = 0; ks < 16; ks++) {
            const int k0 = ks * 8;
            qf[ks][0] = __float_as_uint(Qtmp[(sr + g    ) * FP + k0 + tq    ]);
            qf[ks][1] = __float_as_uint(Qtmp[(sr + g + 8) * FP + k0 + tq    ]);
            qf[ks][2] = __float_as_uint(Qtmp[(sr + g    ) * FP + k0 + tq + 4]);
            qf[ks][3] = __float_as_uint(Qtmp[(sr + g + 8) * FP + k0 + tq + 4]);
        }
    }

    float oc[8][4];
    #pragma unroll
    for (int t = 0; t < 8; t++)
        #pragma unroll
        for (int i = 0; i < 4; i++) oc[t][i] = 0.f;

    for (int kt = 0; kt <= qt; kt++) {
        const float* Ks = smf + (kt % 3) * KVSTRIDE;
        const float* Vs = Ks + 8448;

        if (kt < qt) {
            issueKV(kt + 1, (kt + 1) % 3);
            CP_WAIT(1);
        } else {
            CP_WAIT(0);
        }
        __syncthreads();

        {
            float sc[4][4] = {};
            const int sn0 = wc * 32;
            #pragma unroll
            for (int ks = 0; ks < 16; ks++) {
                const int k0 = ks * 8;
                #pragma unroll
                for (int t = 0; t < 4; t++) {
                    uint32_t bf[2];
                    bf[0] = __float_as_uint(Ks[(sn0 + t * 8 + g) * FP + k0 + tq    ]);
                    bf[1] = __float_as_uint(Ks[(sn0 + t * 8 + g) * FP + k0 + tq + 4]);
                    mma_tf32(sc[t], qf[ks], bf);
                }
            }
            #pragma unroll
            for (int t = 0; t < 4; t++) {
                *(float2*)&Ss[(sr + g    ) * SP + sn0 + t * 8 + 2 * tq] =
                    make_float2(sc[t][0], sc[t][1]);
                *(float2*)&Ss[(sr + g + 8) * SP + sn0 + t * 8 + 2 * tq] =
                    make_float2(sc[t][2], sc[t][3]);
            }
        }
        __syncthreads();

        {
            const int row = tid >> 2;
            const int q4  = tid & 3;
            const int c0  = q4 * 16;
            float s[16];
            #pragma unroll
            for (int j = 0; j < 16; j++) {
                float v = Ss[row * SP + c0 + j] * scale;
                if (kt == qt && (c0 + j) > row) v = -1e30f;
                s[j] = v;
            }
            float mt = s[0];
            #pragma unroll
            for (int j = 1; j < 16; j++) mt = fmaxf(mt, s[j]);
            mt = fmaxf(mt, __shfl_xor_sync(0xffffffffu, mt, 1));
            mt = fmaxf(mt, __shfl_xor_sync(0xffffffffu, mt, 2));
            const float m_old = mrow[row];
            const float mnew  = fmaxf(m_old, mt);
            const float alpha = __expf(m_old - mnew);
            float rs = 0.f;
            #pragma unroll
            for (int j = 0; j < 16; j++) {
                float p = __expf(s[j] - mnew);
                rs += p;
                Ss[row * SP + c0 + j] = wmma::__float_to_tf32(p);
            }
            rs += __shfl_xor_sync(0xffffffffu, rs, 1);
            rs += __shfl_xor_sync(0xffffffffu, rs, 2);
            if (q4 == 0) {
                lrow[row] = lrow[row] * alpha + rs;
                mrow[row] = mnew;
                arow[row] = alpha;
            }
        }
        __syncthreads();

        {
            const float a_lo = arow[sr + g], a_hi = arow[sr + g + 8];
            #pragma unroll
            for (int t = 0; t < 8; t++) {
                oc[t][0] *= a_lo; oc[t][1] *= a_lo;
                oc[t][2] *= a_hi; oc[t][3] *= a_hi;
            }
            const int on0 = wc * 64;
            #pragma unroll
            for (int ks = 0; ks < 8; ks++) {
                const int k0 = ks * 8;
                uint32_t a[4];
                a[0] = __float_as_uint(Ss[(sr + g    ) * SP + k0 + tq    ]);
                a[1] = __float_as_uint(Ss[(sr + g + 8) * SP + k0 + tq    ]);
                a[2] = __float_as_uint(Ss[(sr + g    ) * SP + k0 + tq + 4]);
                a[3] = __float_as_uint(Ss[(sr + g + 8) * SP + k0 + tq + 4]);
                #pragma unroll
                for (int t = 0; t < 8; t++) {
                    uint32_t bf[2];
                    bf[0] = __float_as_uint(Vs[(k0 + tq    ) * FP + on0 + t * 8 + g]);
                    bf[1] = __float_as_uint(Vs[(k0 + tq + 4) * FP + on0 + t * 8 + g]);
                    mma_tf32(oc[t], a, bf);
                }
            }
        }
    }
    __syncthreads();

    {
        const int on0 = wc * 64;
        const float inv_lo = 1.0f / lrow[sr + g];
        const float inv_hi = 1.0f / lrow[sr + g + 8];
        float* Obase = g_attn + ((size_t)b * SEQ + qt * 64) * DM + h * DH;
        #pragma unroll
        for (int t = 0; t < 8; t++) {
            const int col = on0 + t * 8 + 2 * tq;
            float2 lo = make_float2(wmma::__float_to_tf32(oc[t][0] * inv_lo),
                                    wmma::__float_to_tf32(oc[t][1] * inv_lo));
            float2 hi = make_float2(wmma::__float_to_tf32(oc[t][2] * inv_hi),
                                    wmma::__float_to_tf32(oc[t][3] * inv_hi));
            *(float2*)(Obase + (size_t)(sr + g    ) * DM + col) = lo;
            *(float2*)(Obase + (size_t)(sr + g + 8) * DM + col) = hi;
        }
    }
}

// ---------------------------------------------------------------------------
extern "C" void kernel_launch(void* const* d_in, const int* in_sizes, int n_in,
                              void* d_out, int out_size)
{
    const float* x    = (const float*)d_in[0];
    const float* Wqkv = (const float*)d_in[1];
    const float* bqkv = (const float*)d_in[2];
    const float* Wout = (const float*)d_in[3];
    const float* bout = (const float*)d_in[4];
    float* out = (float*)d_out;

    const int M = BATCH * SEQ;

    cudaFuncSetAttribute(gemm_tf32_kernel<0>,
                         cudaFuncAttributeMaxDynamicSharedMemorySize, GEMM_SMEM);
    cudaFuncSetAttribute(gemm_tf32_kernel<1>,
                         cudaFuncAttributeMaxDynamicSharedMemorySize, GEMM_SMEM);
    cudaFuncSetAttribute(flash_kernel,
                         cudaFuncAttributeMaxDynamicSharedMemorySize, FLASH_SMEM);

    float* xt; float* wq; float* wo;
    cudaGetSymbolAddress((void**)&xt, g_xt);
    cudaGetSymbolAddress((void**)&wq, g_wq);
    cudaGetSymbolAddress((void**)&wo, g_wo);

    // 0) pre-pass: round x; transpose+round weights to [N,K]
    cvt_tf32_kernel<<<(int)((size_t)BATCH*SEQ*DM/4/256), 256>>>(x, xt, (int)((size_t)BATCH*SEQ*DM/4));
    {
        dim3 blk(32, 8);
        transpose_tf32_kernel<<<dim3((3*DM)/32, DM/32), blk>>>(Wqkv, wq, DM, 3*DM);
        transpose_tf32_kernel<<<dim3(DM/32, DM/32), blk>>>(Wout, wo, DM, DM);
    }

    // 1) QKV projection (ldmatrix + raw mma), scatter epilogue
    {
        dim3 grid((3 * DM) / 128, M / 128);
        gemm_tf32_kernel<0><<<grid, 256, GEMM_SMEM>>>(xt, wq, bqkv, nullptr, M, 3 * DM, DM);
    }
    // 2) flash attention v3 (unchanged)
    {
        dim3 grid(SEQ / 64, NH, BATCH);
        flash_kernel<<<grid, 256, FLASH_SMEM>>>();
    }
    // 3) output projection -> d_out
    {
        dim3 grid(DM / 128, M / 128);
        gemm_tf32_kernel<1><<<grid, 256, GEMM_SMEM>>>(nullptr, wo, bout, out, M, DM, DM);
    }
}

// round 9
// speedup vs baseline: 1.3687x; 1.3687x over previous
#include <cuda_runtime.h>
#include <mma.h>
#include <math.h>
#include <stdint.h>

using namespace nvcuda;

#define BATCH 2
#define SEQ   2048
#define NH    16
#define DH    128
#define DM    2048
#define NQ    ((size_t)BATCH*NH*SEQ*DH)

__device__ float g_qkv[3*(size_t)BATCH*NH*SEQ*DH];
__device__ float g_attn[(size_t)BATCH*SEQ*DM];
__device__ float g_xt[(size_t)BATCH*SEQ*DM];
__device__ float g_wq[(size_t)DM*3*DM];   // W_qkv^T [6144][2048] tf32 (for ldsm gemm)
__device__ float g_wo[(size_t)DM*DM];     // W_out   [2048][2048] tf32 (row-major, wmma gemm)

// ---------------------------------------------------------------------------
__device__ __forceinline__ uint32_t smem_u32(const void* p) {
    return (uint32_t)__cvta_generic_to_shared(p);
}
#define CP_ASYNC16(dst_u32, src_ptr) \
    asm volatile("cp.async.cg.shared.global [%0], [%1], 16;" :: "r"(dst_u32), "l"(src_ptr))
#define CP_COMMIT()   asm volatile("cp.async.commit_group;")
#define CP_WAIT(n)    asm volatile("cp.async.wait_group %0;" :: "n"(n))

// m16n8k8 tf32 mma, D += A*B
__device__ __forceinline__ void mma_tf32(float* d, const uint32_t* a, const uint32_t* b) {
    asm volatile(
        "mma.sync.aligned.m16n8k8.row.col.f32.tf32.tf32.f32 "
        "{%0,%1,%2,%3},{%4,%5,%6,%7},{%8,%9},{%0,%1,%2,%3};"
        : "+f"(d[0]), "+f"(d[1]), "+f"(d[2]), "+f"(d[3])
        : "r"(a[0]), "r"(a[1]), "r"(a[2]), "r"(a[3]), "r"(b[0]), "r"(b[1]));
}

// ldmatrix x4
__device__ __forceinline__ void ldsm4(uint32_t* r, uint32_t addr) {
    asm volatile("ldmatrix.sync.aligned.m8n8.x4.shared.b16 {%0,%1,%2,%3}, [%4];"
        : "=r"(r[0]), "=r"(r[1]), "=r"(r[2]), "=r"(r[3]) : "r"(addr));
}

// ---------------------------------------------------------------------------
// pre-passes
// ---------------------------------------------------------------------------
__global__ void cvt_tf32_kernel(const float* __restrict__ in,
                                float* __restrict__ out, int n4)
{
    int i = blockIdx.x * blockDim.x + threadIdx.x;
    if (i < n4) {
        float4 v = ((const float4*)in)[i];
        v.x = wmma::__float_to_tf32(v.x); v.y = wmma::__float_to_tf32(v.y);
        v.z = wmma::__float_to_tf32(v.z); v.w = wmma::__float_to_tf32(v.w);
        ((float4*)out)[i] = v;
    }
}

__global__ void transpose_tf32_kernel(const float* __restrict__ in,
                                      float* __restrict__ out, int R, int C)
{
    __shared__ float t[32][33];
    const int c0 = blockIdx.x * 32, r0 = blockIdx.y * 32;
    #pragma unroll
    for (int i = 0; i < 32; i += 8)
        t[threadIdx.y + i][threadIdx.x] =
            in[(size_t)(r0 + threadIdx.y + i) * C + c0 + threadIdx.x];
    __syncthreads();
    #pragma unroll
    for (int i = 0; i < 32; i += 8)
        out[(size_t)(c0 + threadIdx.y + i) * R + r0 + threadIdx.x] =
            wmma::__float_to_tf32(t[threadIdx.x][threadIdx.y + i]);
}

// ---------------------------------------------------------------------------
// QKV GEMM: raw m16n8k8 + ldmatrix feed (round-8 proven, MODE 0 only).
// C = A[M,K] @ Bt[N,K]^T + bias -> scatter into g_qkv (tf32-rounded).
// ---------------------------------------------------------------------------
#define GP 36
#define LSTAGE_F (2*128*GP)
#define LSTAGE_B (LSTAGE_F*4)
#define A_BYTES  (128*GP*4)
#define CS_PITCH 132
#define LGEMM_SMEM (3*LSTAGE_B)   // 110592 B

__global__ __launch_bounds__(256, 2)
void gemm_ldsm_kernel(const float* __restrict__ Aglob, const float* __restrict__ Bt,
                      const float* __restrict__ bias,
                      int M, int N, int K)
{
    extern __shared__ float sm[];
    float* Cs = sm;

    const int tid  = threadIdx.x;
    const int warp = tid >> 5, lane = tid & 31;
    const int wr   = warp >> 1;
    const int wc   = warp & 1;
    const int g    = lane >> 2, tq = lane & 3;
    const int rowBlock = blockIdx.y * 128;
    const int colBlock = blockIdx.x * 128;

    const int ldRow  = tid >> 1;
    const int ldHalf = (tid & 1) * 16;
    const float* Asrc = Aglob + (size_t)(rowBlock + ldRow) * K + ldHalf;
    const float* Bsrc = Bt + (size_t)(colBlock + ldRow) * K + ldHalf;

    const uint32_t smBase = smem_u32(sm);
    const uint32_t ldOff  = (uint32_t)((ldRow * GP + ldHalf) * 4);

    uint32_t aOff[2];
    #pragma unroll
    for (int mi = 0; mi < 2; mi++)
        aOff[mi] = (uint32_t)(((wr * 32 + mi * 16 + (lane & 15)) * GP + (lane >> 4) * 4) * 4);
    uint32_t bOff[4];
    #pragma unroll
    for (int p = 0; p < 4; p++)
        bOff[p] = (uint32_t)(A_BYTES +
                  ((wc * 64 + p * 16 + (lane & 7) + ((lane >> 4) << 3)) * GP
                   + ((lane >> 3) & 1) * 4) * 4);

    float acc[2][8][4] = {};
    const int NIT = K >> 5;

    auto issue = [&](int tt, int s) {
        const int k0 = tt << 5;
        const uint32_t sb = smBase + (uint32_t)s * LSTAGE_B;
        #pragma unroll
        for (int i = 0; i < 4; i++)
            CP_ASYNC16(sb + ldOff + (uint32_t)(i * 16), Asrc + k0 + i * 4);
        #pragma unroll
        for (int i = 0; i < 4; i++)
            CP_ASYNC16(sb + (uint32_t)A_BYTES + ldOff + (uint32_t)(i * 16), Bsrc + k0 + i * 4);
        CP_COMMIT();
    };

    issue(0, 0);

    for (int t = 0; t < NIT; t++) {
        if (t + 1 < NIT) {
            issue(t + 1, (t + 1) % 3);
            CP_WAIT(1);
        } else {
            CP_WAIT(0);
        }
        __syncthreads();

        const uint32_t sb = smBase + (uint32_t)(t % 3) * LSTAGE_B;
        #pragma unroll
        for (int ks = 0; ks < 4; ks++) {
            const uint32_t kb = (uint32_t)(ks * 32);
            uint32_t a0[4], a1[4];
            ldsm4(a0, sb + aOff[0] + kb);
            ldsm4(a1, sb + aOff[1] + kb);
            #pragma unroll
            for (int p = 0; p < 4; p++) {
                uint32_t bb[4];
                ldsm4(bb, sb + bOff[p] + kb);
                mma_tf32(acc[0][2*p  ], a0, bb);
                mma_tf32(acc[0][2*p+1], a0, bb + 2);
                mma_tf32(acc[1][2*p  ], a1, bb);
                mma_tf32(acc[1][2*p+1], a1, bb + 2);
            }
        }
    }
    __syncthreads();

    #pragma unroll
    for (int mi = 0; mi < 2; mi++) {
        const int r_lo = wr * 32 + mi * 16 + g;
        #pragma unroll
        for (int j = 0; j < 8; j++) {
            const int col = wc * 64 + j * 8 + 2 * tq;
            *(float2*)&Cs[r_lo * CS_PITCH + col] =
                make_float2(acc[mi][j][0], acc[mi][j][1]);
            *(float2*)&Cs[(r_lo + 8) * CS_PITCH + col] =
                make_float2(acc[mi][j][2], acc[mi][j][3]);
        }
    }
    __syncthreads();

    #pragma unroll
    for (int it = 0; it < 16; it++) {
        int u = tid + it * 256;
        int row = u >> 5, c4 = (u & 31) * 4;
        float4 v = *(float4*)&Cs[row * CS_PITCH + c4];
        const int gcol = colBlock + c4;
        v.x += bias[gcol + 0]; v.y += bias[gcol + 1];
        v.z += bias[gcol + 2]; v.w += bias[gcol + 3];
        const int gr = rowBlock + row;
        v.x = wmma::__float_to_tf32(v.x); v.y = wmma::__float_to_tf32(v.y);
        v.z = wmma::__float_to_tf32(v.z); v.w = wmma::__float_to_tf32(v.w);
        const int part = gcol >> 11;
        const int c2   = gcol & 2047;
        const int h    = c2 >> 7;
        const int d0   = c2 & 127;
        const int bb   = gr >> 11;
        const int s    = gr & 2047;
        float* dst = g_qkv + (size_t)part * NQ
                   + (((size_t)(bb * NH + h) * SEQ) + s) * DH + d0;
        *(float4*)dst = v;
    }
}

// ---------------------------------------------------------------------------
// Out-projection GEMM: round-7 proven wmma 3-stage kernel (B row-major [K][N]).
// C[M,N] = g_attn[M,K] @ B[K,N] + bias, fp32 row-major out.
// ---------------------------------------------------------------------------
#define WAS_PITCH 36
#define WBS_PITCH 132
#define WSTAGE_F  (128*WAS_PITCH + 32*WBS_PITCH)
#define WGEMM_SMEM (3*WSTAGE_F*4)   // 105984 B

__global__ __launch_bounds__(256, 2)
void gemm_wmma_kernel(const float* __restrict__ B,
                      const float* __restrict__ bias, float* __restrict__ C,
                      int M, int N, int K)
{
    extern __shared__ float sm[];
    float* Cs = sm;

    const float* Abase = (const float*)g_attn;

    const int tid  = threadIdx.x;
    const int warp = tid >> 5;
    const int wr   = warp >> 1;
    const int wc   = warp & 1;
    const int rowBlock = blockIdx.y * 128;
    const int colBlock = blockIdx.x * 128;

    const int aRow0 = tid >> 3;
    const int aCol  = (tid & 7) * 4;
    const int bRow0 = tid >> 5;
    const int bCol  = (tid & 31) * 4;

    const float* Asrc = Abase + (size_t)(rowBlock + aRow0) * K + aCol;
    const float* Bsrc = B + (size_t)bRow0 * N + colBlock + bCol;

    const uint32_t smBase = smem_u32(sm);
    const uint32_t aOffB  = (uint32_t)((aRow0 * WAS_PITCH + aCol) * 4);
    const uint32_t bOffB  = (uint32_t)((128 * WAS_PITCH + bRow0 * WBS_PITCH + bCol) * 4);

    wmma::fragment<wmma::accumulator, 16, 16, 8, float> acc[2][4];
    #pragma unroll
    for (int i = 0; i < 2; i++)
        #pragma unroll
        for (int j = 0; j < 4; j++)
            wmma::fill_fragment(acc[i][j], 0.0f);

    const int NIT = K >> 5;

    auto issue = [&](int tt, int s) {
        const int k0 = tt << 5;
        const uint32_t sb = smBase + (uint32_t)s * (WSTAGE_F * 4);
        #pragma unroll
        for (int it = 0; it < 4; it++)
            CP_ASYNC16(sb + aOffB + (uint32_t)(it * 32 * WAS_PITCH * 4),
                       Asrc + (size_t)(it * 32) * K + k0);
        #pragma unroll
        for (int it = 0; it < 4; it++)
            CP_ASYNC16(sb + bOffB + (uint32_t)(it * 8 * WBS_PITCH * 4),
                       Bsrc + (size_t)(k0 + it * 8) * N);
        CP_COMMIT();
    };

    issue(0, 0);

    for (int t = 0; t < NIT; t++) {
        if (t + 1 < NIT) {
            issue(t + 1, (t + 1) % 3);
            CP_WAIT(1);
        } else {
            CP_WAIT(0);
        }
        __syncthreads();

        const float* As = sm + (t % 3) * WSTAGE_F;
        const float* Bs = As + 128 * WAS_PITCH;
        #pragma unroll
        for (int ks = 0; ks < 4; ks++) {
            wmma::fragment<wmma::matrix_a, 16, 16, 8, wmma::precision::tf32, wmma::row_major> af[2];
            wmma::fragment<wmma::matrix_b, 16, 16, 8, wmma::precision::tf32, wmma::row_major> bf[4];
            #pragma unroll
            for (int i = 0; i < 2; i++)
                wmma::load_matrix_sync(af[i], &As[(wr * 32 + i * 16) * WAS_PITCH + ks * 8], WAS_PITCH);
            #pragma unroll
            for (int j = 0; j < 4; j++)
                wmma::load_matrix_sync(bf[j], &Bs[(ks * 8) * WBS_PITCH + wc * 64 + j * 16], WBS_PITCH);
            #pragma unroll
            for (int i = 0; i < 2; i++)
                #pragma unroll
                for (int j = 0; j < 4; j++)
                    wmma::mma_sync(acc[i][j], af[i], bf[j], acc[i][j]);
        }
    }
    __syncthreads();

    #pragma unroll
    for (int i = 0; i < 2; i++)
        #pragma unroll
        for (int j = 0; j < 4; j++)
            wmma::store_matrix_sync(&Cs[(wr * 32 + i * 16) * CS_PITCH + wc * 64 + j * 16],
                                    acc[i][j], CS_PITCH, wmma::mem_row_major);
    __syncthreads();

    #pragma unroll
    for (int it = 0; it < 16; it++) {
        int u = tid + it * 256;
        int row = u >> 5, c4 = (u & 31) * 4;
        float4 v = *(float4*)&Cs[row * CS_PITCH + c4];
        const int gcol = colBlock + c4;
        v.x += bias[gcol + 0]; v.y += bias[gcol + 1];
        v.z += bias[gcol + 2]; v.w += bias[gcol + 3];
        const int gr = rowBlock + row;
        *(float4*)(C + (size_t)gr * N + gcol) = v;
    }
}

// ---------------------------------------------------------------------------
// Causal flash attention v3 (round-7/8 proven, unchanged).
// ---------------------------------------------------------------------------
#define FP 132
#define SP 68
#define KVSTRIDE (2*8448)
#define FLASH_SMEM ((6*8448 + 64*SP + 192) * 4)

__global__ __launch_bounds__(256)
void flash_kernel()
{
    extern __shared__ float smf[];
    float* Ss   = smf + 6 * 8448;
    float* mrow = Ss + 64 * SP;
    float* lrow = mrow + 64;
    float* arow = lrow + 64;

    const int qt = blockIdx.x, h = blockIdx.y, b = blockIdx.z;
    const int bh = b * NH + h;

    const float* Qp = g_qkv + 0 * NQ + ((size_t)bh * SEQ + qt * 64) * DH;
    const float* Kp = g_qkv + 1 * NQ + (size_t)bh * SEQ * DH;
    const float* Vp = g_qkv + 2 * NQ + (size_t)bh * SEQ * DH;

    const int tid  = threadIdx.x;
    const int warp = tid >> 5, lane = tid & 31;
    const int wr = warp >> 1, wc = warp & 1;
    const int g  = lane >> 2, tq = lane & 3;
    const int sr = wr * 16;

    const float scale = 0.08838834764831845f;

    auto issueKV = [&](int kt, int s) {
        const float* Kt = Kp + (size_t)kt * 64 * DH;
        const float* Vt = Vp + (size_t)kt * 64 * DH;
        float* Kd = smf + s * KVSTRIDE;
        float* Vd = Kd + 8448;
        #pragma unroll
        for (int it = 0; it < 8; it++) {
            int u = tid + it * 256;
            int r = u >> 5, c = (u & 31) * 4;
            CP_ASYNC16(smem_u32(&Kd[r * FP + c]), Kt + r * DH + c);
            CP_ASYNC16(smem_u32(&Vd[r * FP + c]), Vt + r * DH + c);
        }
        CP_COMMIT();
    };

    issueKV(0, 0);
    {
        float* Qtmp = smf + 2 * KVSTRIDE + 8448;
        #pragma unroll
        for (int it = 0; it < 8; it++) {
            int u = tid + it * 256;
            int r = u >> 5, c = (u & 31) * 4;
            *(float4*)&Qtmp[r * FP + c] = *(const float4*)(Qp + r * DH + c);
        }
    }
    if (tid < 64) { mrow[tid] = -1e30f; lrow[tid] = 0.f; }
    __syncthreads();

    uint32_t qf[16][4];
    {
        const float* Qtmp = smf + 2 * KVSTRIDE + 8448;
        #pragma unroll
        for (int ks = 0; ks < 16; ks++) {
            const int k0 = ks * 8;
            qf[ks][0] = __float_as_uint(Qtmp[(sr + g    ) * FP + k0 + tq    ]);
            qf[ks][1] = __float_as_uint(Qtmp[(sr + g + 8) * FP + k0 + tq    ]);
            qf[ks][2] = __float_as_uint(Qtmp[(sr + g    ) * FP + k0 + tq + 4]);
            qf[ks][3] = __float_as_uint(Qtmp[(sr + g + 8) * FP + k0 + tq + 4]);
        }
    }

    float oc[8][4];
    #pragma unroll
    for (int t = 0; t < 8; t++)
        #pragma unroll
        for (int i = 0; i < 4; i++) oc[t][i] = 0.f;

    for (int kt = 0; kt <= qt; kt++) {
        const float* Ks = smf + (kt % 3) * KVSTRIDE;
        const float* Vs = Ks + 8448;

        if (kt < qt) {
            issueKV(kt + 1, (kt + 1) % 3);
            CP_WAIT(1);
        } else {
            CP_WAIT(0);
        }
        __syncthreads();

        {
            float sc[4][4] = {};
            const int sn0 = wc * 32;
            #pragma unroll
            for (int ks = 0; ks < 16; ks++) {
                const int k0 = ks * 8;
                #pragma unroll
                for (int t = 0; t < 4; t++) {
                    uint32_t bf[2];
                    bf[0] = __float_as_uint(Ks[(sn0 + t * 8 + g) * FP + k0 + tq    ]);
                    bf[1] = __float_as_uint(Ks[(sn0 + t * 8 + g) * FP + k0 + tq + 4]);
                    mma_tf32(sc[t], qf[ks], bf);
                }
            }
            #pragma unroll
            for (int t = 0; t < 4; t++) {
                *(float2*)&Ss[(sr + g    ) * SP + sn0 + t * 8 + 2 * tq] =
                    make_float2(sc[t][0], sc[t][1]);
                *(float2*)&Ss[(sr + g + 8) * SP + sn0 + t * 8 + 2 * tq] =
                    make_float2(sc[t][2], sc[t][3]);
            }
        }
        __syncthreads();

        {
            const int row = tid >> 2;
            const int q4  = tid & 3;
            const int c0  = q4 * 16;
            float s[16];
            #pragma unroll
            for (int j = 0; j < 16; j++) {
                float v = Ss[row * SP + c0 + j] * scale;
                if (kt == qt && (c0 + j) > row) v = -1e30f;
                s[j] = v;
            }
            float mt = s[0];
            #pragma unroll
            for (int j = 1; j < 16; j++) mt = fmaxf(mt, s[j]);
            mt = fmaxf(mt, __shfl_xor_sync(0xffffffffu, mt, 1));
            mt = fmaxf(mt, __shfl_xor_sync(0xffffffffu, mt, 2));
            const float m_old = mrow[row];
            const float mnew  = fmaxf(m_old, mt);
            const float alpha = __expf(m_old - mnew);
            float rs = 0.f;
            #pragma unroll
            for (int j = 0; j < 16; j++) {
                float p = __expf(s[j] - mnew);
                rs += p;
                Ss[row * SP + c0 + j] = wmma::__float_to_tf32(p);
            }
            rs += __shfl_xor_sync(0xffffffffu, rs, 1);
            rs += __shfl_xor_sync(0xffffffffu, rs, 2);
            if (q4 == 0) {
                lrow[row] = lrow[row] * alpha + rs;
                mrow[row] = mnew;
                arow[row] = alpha;
            }
        }
        __syncthreads();

        {
            const float a_lo = arow[sr + g], a_hi = arow[sr + g + 8];
            #pragma unroll
            for (int t = 0; t < 8; t++) {
                oc[t][0] *= a_lo; oc[t][1] *= a_lo;
                oc[t][2] *= a_hi; oc[t][3] *= a_hi;
            }
            const int on0 = wc * 64;
            #pragma unroll
            for (int ks = 0; ks < 8; ks++) {
                const int k0 = ks * 8;
                uint32_t a[4];
                a[0] = __float_as_uint(Ss[(sr + g    ) * SP + k0 + tq    ]);
                a[1] = __float_as_uint(Ss[(sr + g + 8) * SP + k0 + tq    ]);
                a[2] = __float_as_uint(Ss[(sr + g    ) * SP + k0 + tq + 4]);
                a[3] = __float_as_uint(Ss[(sr + g + 8) * SP + k0 + tq + 4]);
                #pragma unroll
                for (int t = 0; t < 8; t++) {
                    uint32_t bf[2];
                    bf[0] = __float_as_uint(Vs[(k0 + tq    ) * FP + on0 + t * 8 + g]);
                    bf[1] = __float_as_uint(Vs[(k0 + tq + 4) * FP + on0 + t * 8 + g]);
                    mma_tf32(oc[t], a, bf);
                }
            }
        }
    }
    __syncthreads();

    {
        const int on0 = wc * 64;
        const float inv_lo = 1.0f / lrow[sr + g];
        const float inv_hi = 1.0f / lrow[sr + g + 8];
        float* Obase = g_attn + ((size_t)b * SEQ + qt * 64) * DM + h * DH;
        #pragma unroll
        for (int t = 0; t < 8; t++) {
            const int col = on0 + t * 8 + 2 * tq;
            float2 lo = make_float2(wmma::__float_to_tf32(oc[t][0] * inv_lo),
                                    wmma::__float_to_tf32(oc[t][1] * inv_lo));
            float2 hi = make_float2(wmma::__float_to_tf32(oc[t][2] * inv_hi),
                                    wmma::__float_to_tf32(oc[t][3] * inv_hi));
            *(float2*)(Obase + (size_t)(sr + g    ) * DM + col) = lo;
            *(float2*)(Obase + (size_t)(sr + g + 8) * DM + col) = hi;
        }
    }
}

// ---------------------------------------------------------------------------
extern "C" void kernel_launch(void* const* d_in, const int* in_sizes, int n_in,
                              void* d_out, int out_size)
{
    const float* x    = (const float*)d_in[0];
    const float* Wqkv = (const float*)d_in[1];
    const float* bqkv = (const float*)d_in[2];
    const float* Wout = (const float*)d_in[3];
    const float* bout = (const float*)d_in[4];
    float* out = (float*)d_out;

    const int M = BATCH * SEQ;

    cudaFuncSetAttribute(gemm_ldsm_kernel,
                         cudaFuncAttributeMaxDynamicSharedMemorySize, LGEMM_SMEM);
    cudaFuncSetAttribute(gemm_wmma_kernel,
                         cudaFuncAttributeMaxDynamicSharedMemorySize, WGEMM_SMEM);
    cudaFuncSetAttribute(flash_kernel,
                         cudaFuncAttributeMaxDynamicSharedMemorySize, FLASH_SMEM);

    float* xt; float* wq; float* wo;
    cudaGetSymbolAddress((void**)&xt, g_xt);
    cudaGetSymbolAddress((void**)&wq, g_wq);
    cudaGetSymbolAddress((void**)&wo, g_wo);

    // 0) pre-pass: cvt x; transpose W_qkv -> [N][K]; cvt W_out (stays [K][N])
    cvt_tf32_kernel<<<(int)((size_t)BATCH*SEQ*DM/4/256), 256>>>(x, xt, (int)((size_t)BATCH*SEQ*DM/4));
    {
        dim3 blk(32, 8);
        transpose_tf32_kernel<<<dim3((3*DM)/32, DM/32), blk>>>(Wqkv, wq, DM, 3*DM);
    }
    cvt_tf32_kernel<<<(int)((size_t)DM*DM/4/256), 256>>>(Wout, wo, (int)((size_t)DM*DM/4));

    // 1) QKV projection (ldmatrix + raw mma), scatter epilogue
    {
        dim3 grid((3 * DM) / 128, M / 128);
        gemm_ldsm_kernel<<<grid, 256, LGEMM_SMEM>>>(xt, wq, bqkv, M, 3 * DM, DM);
    }
    // 2) flash attention v3 (unchanged)
    {
        dim3 grid(SEQ / 64, NH, BATCH);
        flash_kernel<<<grid, 256, FLASH_SMEM>>>();
    }
    // 3) output projection (round-7 wmma) -> d_out
    {
        dim3 grid(DM / 128, M / 128);
        gemm_wmma_kernel<<<grid, 256, WGEMM_SMEM>>>(wo, bout, out, M, DM, DM);
    }
}

// round 10
// speedup vs baseline: 1.3711x; 1.0018x over previous
#include <cuda_runtime.h>
#include <mma.h>
#include <math.h>
#include <stdint.h>

using namespace nvcuda;

#define BATCH 2
#define SEQ   2048
#define NH    16
#define DH    128
#define DM    2048
#define NQ    ((size_t)BATCH*NH*SEQ*DH)

__device__ float g_qkv[3*(size_t)BATCH*NH*SEQ*DH];
__device__ float g_attn[(size_t)BATCH*SEQ*DM];
__device__ float g_xt[(size_t)BATCH*SEQ*DM];
__device__ float g_wq[(size_t)DM*3*DM];   // W_qkv^T [6144][2048] tf32 (ldsm gemm)
__device__ float g_wo[(size_t)DM*DM];     // W_out   [2048][2048] tf32 (wmma gemm)

// ---------------------------------------------------------------------------
__device__ __forceinline__ uint32_t smem_u32(const void* p) {
    return (uint32_t)__cvta_generic_to_shared(p);
}
#define CP_ASYNC16(dst_u32, src_ptr) \
    asm volatile("cp.async.cg.shared.global [%0], [%1], 16;" :: "r"(dst_u32), "l"(src_ptr))
#define CP_COMMIT()   asm volatile("cp.async.commit_group;")
#define CP_WAIT(n)    asm volatile("cp.async.wait_group %0;" :: "n"(n))

// m16n8k8 tf32 mma, D += A*B
__device__ __forceinline__ void mma_tf32(float* d, const uint32_t* a, const uint32_t* b) {
    asm volatile(
        "mma.sync.aligned.m16n8k8.row.col.f32.tf32.tf32.f32 "
        "{%0,%1,%2,%3},{%4,%5,%6,%7},{%8,%9},{%0,%1,%2,%3};"
        : "+f"(d[0]), "+f"(d[1]), "+f"(d[2]), "+f"(d[3])
        : "r"(a[0]), "r"(a[1]), "r"(a[2]), "r"(a[3]), "r"(b[0]), "r"(b[1]));
}

// ldmatrix x4
__device__ __forceinline__ void ldsm4(uint32_t* r, uint32_t addr) {
    asm volatile("ldmatrix.sync.aligned.m8n8.x4.shared.b16 {%0,%1,%2,%3}, [%4];"
        : "=r"(r[0]), "=r"(r[1]), "=r"(r[2]), "=r"(r[3]) : "r"(addr));
}

// ---------------------------------------------------------------------------
// pre-passes
// ---------------------------------------------------------------------------
__global__ void cvt_tf32_kernel(const float* __restrict__ in,
                                float* __restrict__ out, int n4)
{
    int i = blockIdx.x * blockDim.x + threadIdx.x;
    if (i < n4) {
        float4 v = ((const float4*)in)[i];
        v.x = wmma::__float_to_tf32(v.x); v.y = wmma::__float_to_tf32(v.y);
        v.z = wmma::__float_to_tf32(v.z); v.w = wmma::__float_to_tf32(v.w);
        ((float4*)out)[i] = v;
    }
}

__global__ void transpose_tf32_kernel(const float* __restrict__ in,
                                      float* __restrict__ out, int R, int C)
{
    __shared__ float t[32][33];
    const int c0 = blockIdx.x * 32, r0 = blockIdx.y * 32;
    #pragma unroll
    for (int i = 0; i < 32; i += 8)
        t[threadIdx.y + i][threadIdx.x] =
            in[(size_t)(r0 + threadIdx.y + i) * C + c0 + threadIdx.x];
    __syncthreads();
    #pragma unroll
    for (int i = 0; i < 32; i += 8)
        out[(size_t)(c0 + threadIdx.y + i) * R + r0 + threadIdx.x] =
            wmma::__float_to_tf32(t[threadIdx.x][threadIdx.y + i]);
}

// ---------------------------------------------------------------------------
// QKV GEMM: raw m16n8k8 + ldmatrix feed (round-8/9 proven).
// ---------------------------------------------------------------------------
#define GP 36
#define LSTAGE_F (2*128*GP)
#define LSTAGE_B (LSTAGE_F*4)
#define A_BYTES  (128*GP*4)
#define CS_PITCH 132
#define LGEMM_SMEM (3*LSTAGE_B)   // 110592 B

__global__ __launch_bounds__(256, 2)
void gemm_ldsm_kernel(const float* __restrict__ Aglob, const float* __restrict__ Bt,
                      const float* __restrict__ bias,
                      int M, int N, int K)
{
    extern __shared__ float sm[];
    float* Cs = sm;

    const int tid  = threadIdx.x;
    const int warp = tid >> 5, lane = tid & 31;
    const int wr   = warp >> 1;
    const int wc   = warp & 1;
    const int g    = lane >> 2, tq = lane & 3;
    const int rowBlock = blockIdx.y * 128;
    const int colBlock = blockIdx.x * 128;

    const int ldRow  = tid >> 1;
    const int ldHalf = (tid & 1) * 16;
    const float* Asrc = Aglob + (size_t)(rowBlock + ldRow) * K + ldHalf;
    const float* Bsrc = Bt + (size_t)(colBlock + ldRow) * K + ldHalf;

    const uint32_t smBase = smem_u32(sm);
    const uint32_t ldOff  = (uint32_t)((ldRow * GP + ldHalf) * 4);

    uint32_t aOff[2];
    #pragma unroll
    for (int mi = 0; mi < 2; mi++)
        aOff[mi] = (uint32_t)(((wr * 32 + mi * 16 + (lane & 15)) * GP + (lane >> 4) * 4) * 4);
    uint32_t bOff[4];
    #pragma unroll
    for (int p = 0; p < 4; p++)
        bOff[p] = (uint32_t)(A_BYTES +
                  ((wc * 64 + p * 16 + (lane & 7) + ((lane >> 4) << 3)) * GP
                   + ((lane >> 3) & 1) * 4) * 4);

    float acc[2][8][4] = {};
    const int NIT = K >> 5;

    auto issue = [&](int tt, int s) {
        const int k0 = tt << 5;
        const uint32_t sb = smBase + (uint32_t)s * LSTAGE_B;
        #pragma unroll
        for (int i = 0; i < 4; i++)
            CP_ASYNC16(sb + ldOff + (uint32_t)(i * 16), Asrc + k0 + i * 4);
        #pragma unroll
        for (int i = 0; i < 4; i++)
            CP_ASYNC16(sb + (uint32_t)A_BYTES + ldOff + (uint32_t)(i * 16), Bsrc + k0 + i * 4);
        CP_COMMIT();
    };

    issue(0, 0);

    for (int t = 0; t < NIT; t++) {
        if (t + 1 < NIT) {
            issue(t + 1, (t + 1) % 3);
            CP_WAIT(1);
        } else {
            CP_WAIT(0);
        }
        __syncthreads();

        const uint32_t sb = smBase + (uint32_t)(t % 3) * LSTAGE_B;
        #pragma unroll
        for (int ks = 0; ks < 4; ks++) {
            const uint32_t kb = (uint32_t)(ks * 32);
            uint32_t a0[4], a1[4];
            ldsm4(a0, sb + aOff[0] + kb);
            ldsm4(a1, sb + aOff[1] + kb);
            #pragma unroll
            for (int p = 0; p < 4; p++) {
                uint32_t bb[4];
                ldsm4(bb, sb + bOff[p] + kb);
                mma_tf32(acc[0][2*p  ], a0, bb);
                mma_tf32(acc[0][2*p+1], a0, bb + 2);
                mma_tf32(acc[1][2*p  ], a1, bb);
                mma_tf32(acc[1][2*p+1], a1, bb + 2);
            }
        }
    }
    __syncthreads();

    #pragma unroll
    for (int mi = 0; mi < 2; mi++) {
        const int r_lo = wr * 32 + mi * 16 + g;
        #pragma unroll
        for (int j = 0; j < 8; j++) {
            const int col = wc * 64 + j * 8 + 2 * tq;
            *(float2*)&Cs[r_lo * CS_PITCH + col] =
                make_float2(acc[mi][j][0], acc[mi][j][1]);
            *(float2*)&Cs[(r_lo + 8) * CS_PITCH + col] =
                make_float2(acc[mi][j][2], acc[mi][j][3]);
        }
    }
    __syncthreads();

    #pragma unroll
    for (int it = 0; it < 16; it++) {
        int u = tid + it * 256;
        int row = u >> 5, c4 = (u & 31) * 4;
        float4 v = *(float4*)&Cs[row * CS_PITCH + c4];
        const int gcol = colBlock + c4;
        v.x += bias[gcol + 0]; v.y += bias[gcol + 1];
        v.z += bias[gcol + 2]; v.w += bias[gcol + 3];
        const int gr = rowBlock + row;
        v.x = wmma::__float_to_tf32(v.x); v.y = wmma::__float_to_tf32(v.y);
        v.z = wmma::__float_to_tf32(v.z); v.w = wmma::__float_to_tf32(v.w);
        const int part = gcol >> 11;
        const int c2   = gcol & 2047;
        const int h    = c2 >> 7;
        const int d0   = c2 & 127;
        const int bb   = gr >> 11;
        const int s    = gr & 2047;
        float* dst = g_qkv + (size_t)part * NQ
                   + (((size_t)(bb * NH + h) * SEQ) + s) * DH + d0;
        *(float4*)dst = v;
    }
}

// ---------------------------------------------------------------------------
// Out-projection GEMM: wmma 3-stage (round-7/9 proven).
// ---------------------------------------------------------------------------
#define WAS_PITCH 36
#define WBS_PITCH 132
#define WSTAGE_F  (128*WAS_PITCH + 32*WBS_PITCH)
#define WGEMM_SMEM (3*WSTAGE_F*4)   // 105984 B

__global__ __launch_bounds__(256, 2)
void gemm_wmma_kernel(const float* __restrict__ B,
                      const float* __restrict__ bias, float* __restrict__ C,
                      int M, int N, int K)
{
    extern __shared__ float sm[];
    float* Cs = sm;

    const float* Abase = (const float*)g_attn;

    const int tid  = threadIdx.x;
    const int warp = tid >> 5;
    const int wr   = warp >> 1;
    const int wc   = warp & 1;
    const int rowBlock = blockIdx.y * 128;
    const int colBlock = blockIdx.x * 128;

    const int aRow0 = tid >> 3;
    const int aCol  = (tid & 7) * 4;
    const int bRow0 = tid >> 5;
    const int bCol  = (tid & 31) * 4;

    const float* Asrc = Abase + (size_t)(rowBlock + aRow0) * K + aCol;
    const float* Bsrc = B + (size_t)bRow0 * N + colBlock + bCol;

    const uint32_t smBase = smem_u32(sm);
    const uint32_t aOffB  = (uint32_t)((aRow0 * WAS_PITCH + aCol) * 4);
    const uint32_t bOffB  = (uint32_t)((128 * WAS_PITCH + bRow0 * WBS_PITCH + bCol) * 4);

    wmma::fragment<wmma::accumulator, 16, 16, 8, float> acc[2][4];
    #pragma unroll
    for (int i = 0; i < 2; i++)
        #pragma unroll
        for (int j = 0; j < 4; j++)
            wmma::fill_fragment(acc[i][j], 0.0f);

    const int NIT = K >> 5;

    auto issue = [&](int tt, int s) {
        const int k0 = tt << 5;
        const uint32_t sb = smBase + (uint32_t)s * (WSTAGE_F * 4);
        #pragma unroll
        for (int it = 0; it < 4; it++)
            CP_ASYNC16(sb + aOffB + (uint32_t)(it * 32 * WAS_PITCH * 4),
                       Asrc + (size_t)(it * 32) * K + k0);
        #pragma unroll
        for (int it = 0; it < 4; it++)
            CP_ASYNC16(sb + bOffB + (uint32_t)(it * 8 * WBS_PITCH * 4),
                       Bsrc + (size_t)(k0 + it * 8) * N);
        CP_COMMIT();
    };

    issue(0, 0);

    for (int t = 0; t < NIT; t++) {
        if (t + 1 < NIT) {
            issue(t + 1, (t + 1) % 3);
            CP_WAIT(1);
        } else {
            CP_WAIT(0);
        }
        __syncthreads();

        const float* As = sm + (t % 3) * WSTAGE_F;
        const float* Bs = As + 128 * WAS_PITCH;
        #pragma unroll
        for (int ks = 0; ks < 4; ks++) {
            wmma::fragment<wmma::matrix_a, 16, 16, 8, wmma::precision::tf32, wmma::row_major> af[2];
            wmma::fragment<wmma::matrix_b, 16, 16, 8, wmma::precision::tf32, wmma::row_major> bf[4];
            #pragma unroll
            for (int i = 0; i < 2; i++)
                wmma::load_matrix_sync(af[i], &As[(wr * 32 + i * 16) * WAS_PITCH + ks * 8], WAS_PITCH);
            #pragma unroll
            for (int j = 0; j < 4; j++)
                wmma::load_matrix_sync(bf[j], &Bs[(ks * 8) * WBS_PITCH + wc * 64 + j * 16], WBS_PITCH);
            #pragma unroll
            for (int i = 0; i < 2; i++)
                #pragma unroll
                for (int j = 0; j < 4; j++)
                    wmma::mma_sync(acc[i][j], af[i], bf[j], acc[i][j]);
        }
    }
    __syncthreads();

    #pragma unroll
    for (int i = 0; i < 2; i++)
        #pragma unroll
        for (int j = 0; j < 4; j++)
            wmma::store_matrix_sync(&Cs[(wr * 32 + i * 16) * CS_PITCH + wc * 64 + j * 16],
                                    acc[i][j], CS_PITCH, wmma::mem_row_major);
    __syncthreads();

    #pragma unroll
    for (int it = 0; it < 16; it++) {
        int u = tid + it * 256;
        int row = u >> 5, c4 = (u & 31) * 4;
        float4 v = *(float4*)&Cs[row * CS_PITCH + c4];
        const int gcol = colBlock + c4;
        v.x += bias[gcol + 0]; v.y += bias[gcol + 1];
        v.z += bias[gcol + 2]; v.w += bias[gcol + 3];
        const int gr = rowBlock + row;
        *(float4*)(C + (size_t)gr * N + gcol) = v;
    }
}

// ---------------------------------------------------------------------------
// Causal flash attention v4: ldmatrix feeds for K (S-gemm B) and P (PV A).
// V feed stays scalar LDS (no 32-bit ldmatrix transpose exists).
// ---------------------------------------------------------------------------
#define FP 132
#define SP 68
#define KVSTRIDE (2*8448)
#define FLASH_SMEM ((6*8448 + 64*SP + 192) * 4)

__global__ __launch_bounds__(256)
void flash_kernel()
{
    extern __shared__ float smf[];
    float* Ss   = smf + 6 * 8448;
    float* mrow = Ss + 64 * SP;
    float* lrow = mrow + 64;
    float* arow = lrow + 64;

    const int qt = blockIdx.x, h = blockIdx.y, b = blockIdx.z;
    const int bh = b * NH + h;

    const float* Qp = g_qkv + 0 * NQ + ((size_t)bh * SEQ + qt * 64) * DH;
    const float* Kp = g_qkv + 1 * NQ + (size_t)bh * SEQ * DH;
    const float* Vp = g_qkv + 2 * NQ + (size_t)bh * SEQ * DH;

    const int tid  = threadIdx.x;
    const int warp = tid >> 5, lane = tid & 31;
    const int wr = warp >> 1, wc = warp & 1;
    const int g  = lane >> 2, tq = lane & 3;
    const int sr = wr * 16;

    const float scale = 0.08838834764831845f;

    // ldmatrix lane-address offsets
    // K (B-operand): n rows at pitch FP; pair p covers n-tiles 2p,2p+1
    const uint32_t kOff0 = (uint32_t)(((wc * 32 + (lane & 7) + ((lane >> 4) << 3)) * FP
                                      + ((lane >> 3) & 1) * 4) * 4);
    const uint32_t kOff1 = kOff0 + (uint32_t)(16 * FP * 4);
    // P (A-operand): rows sr..sr+15 at pitch SP
    const uint32_t pOff  = (uint32_t)(((sr + (lane & 15)) * SP + (lane >> 4) * 4) * 4);
    const uint32_t ssB   = smem_u32(Ss);

    auto issueKV = [&](int kt, int s) {
        const float* Kt = Kp + (size_t)kt * 64 * DH;
        const float* Vt = Vp + (size_t)kt * 64 * DH;
        float* Kd = smf + s * KVSTRIDE;
        float* Vd = Kd + 8448;
        #pragma unroll
        for (int it = 0; it < 8; it++) {
            int u = tid + it * 256;
            int r = u >> 5, c = (u & 31) * 4;
            CP_ASYNC16(smem_u32(&Kd[r * FP + c]), Kt + r * DH + c);
            CP_ASYNC16(smem_u32(&Vd[r * FP + c]), Vt + r * DH + c);
        }
        CP_COMMIT();
    };

    issueKV(0, 0);
    {
        float* Qtmp = smf + 2 * KVSTRIDE + 8448;
        #pragma unroll
        for (int it = 0; it < 8; it++) {
            int u = tid + it * 256;
            int r = u >> 5, c = (u & 31) * 4;
            *(float4*)&Qtmp[r * FP + c] = *(const float4*)(Qp + r * DH + c);
        }
    }
    if (tid < 64) { mrow[tid] = -1e30f; lrow[tid] = 0.f; }
    __syncthreads();

    uint32_t qf[16][4];
    {
        const float* Qtmp = smf + 2 * KVSTRIDE + 8448;
        #pragma unroll
        for (int ks = 0; ks < 16; ks++) {
            const int k0 = ks * 8;
            qf[ks][0] = __float_as_uint(Qtmp[(sr + g    ) * FP + k0 + tq    ]);
            qf[ks][1] = __float_as_uint(Qtmp[(sr + g + 8) * FP + k0 + tq    ]);
            qf[ks][2] = __float_as_uint(Qtmp[(sr + g    ) * FP + k0 + tq + 4]);
            qf[ks][3] = __float_as_uint(Qtmp[(sr + g + 8) * FP + k0 + tq + 4]);
        }
    }

    float oc[8][4];
    #pragma unroll
    for (int t = 0; t < 8; t++)
        #pragma unroll
        for (int i = 0; i < 4; i++) oc[t][i] = 0.f;

    for (int kt = 0; kt <= qt; kt++) {
        const float* Ks = smf + (kt % 3) * KVSTRIDE;
        const float* Vs = Ks + 8448;

        if (kt < qt) {
            issueKV(kt + 1, (kt + 1) % 3);
            CP_WAIT(1);
        } else {
            CP_WAIT(0);
        }
        __syncthreads();

        // ---- S = Q K^T : Q regs, K via ldmatrix ----
        {
            float sc[4][4] = {};
            const uint32_t kBase = smem_u32(Ks);
            #pragma unroll
            for (int ks = 0; ks < 16; ks++) {
                const uint32_t kb = (uint32_t)(ks * 32);
                uint32_t b0[4], b1[4];
                ldsm4(b0, kBase + kOff0 + kb);
                ldsm4(b1, kBase + kOff1 + kb);
                mma_tf32(sc[0], qf[ks], b0);
                mma_tf32(sc[1], qf[ks], b0 + 2);
                mma_tf32(sc[2], qf[ks], b1);
                mma_tf32(sc[3], qf[ks], b1 + 2);
            }
            const int sn0 = wc * 32;
            #pragma unroll
            for (int t = 0; t < 4; t++) {
                *(float2*)&Ss[(sr + g    ) * SP + sn0 + t * 8 + 2 * tq] =
                    make_float2(sc[t][0], sc[t][1]);
                *(float2*)&Ss[(sr + g + 8) * SP + sn0 + t * 8 + 2 * tq] =
                    make_float2(sc[t][2], sc[t][3]);
            }
        }
        __syncthreads();

        // ---- softmax (fp32): 4 lanes/row ----
        {
            const int row = tid >> 2;
            const int q4  = tid & 3;
            const int c0  = q4 * 16;
            float s[16];
            #pragma unroll
            for (int j = 0; j < 16; j++) {
                float v = Ss[row * SP + c0 + j] * scale;
                if (kt == qt && (c0 + j) > row) v = -1e30f;
                s[j] = v;
            }
            float mt = s[0];
            #pragma unroll
            for (int j = 1; j < 16; j++) mt = fmaxf(mt, s[j]);
            mt = fmaxf(mt, __shfl_xor_sync(0xffffffffu, mt, 1));
            mt = fmaxf(mt, __shfl_xor_sync(0xffffffffu, mt, 2));
            const float m_old = mrow[row];
            const float mnew  = fmaxf(m_old, mt);
            const float alpha = __expf(m_old - mnew);
            float rs = 0.f;
            #pragma unroll
            for (int j = 0; j < 16; j++) {
                float p = __expf(s[j] - mnew);
                rs += p;
                Ss[row * SP + c0 + j] = wmma::__float_to_tf32(p);
            }
            rs += __shfl_xor_sync(0xffffffffu, rs, 1);
            rs += __shfl_xor_sync(0xffffffffu, rs, 2);
            if (q4 == 0) {
                lrow[row] = lrow[row] * alpha + rs;
                mrow[row] = mnew;
                arow[row] = alpha;
            }
        }
        __syncthreads();

        // ---- O = O*alpha + P V : P via ldmatrix, V scalar ----
        {
            const float a_lo = arow[sr + g], a_hi = arow[sr + g + 8];
            #pragma unroll
            for (int t = 0; t < 8; t++) {
                oc[t][0] *= a_lo; oc[t][1] *= a_lo;
                oc[t][2] *= a_hi; oc[t][3] *= a_hi;
            }
            const int on0 = wc * 64;
            #pragma unroll
            for (int ks = 0; ks < 8; ks++) {
                const int k0 = ks * 8;
                uint32_t a[4];
                ldsm4(a, ssB + pOff + (uint32_t)(ks * 32));
                #pragma unroll
                for (int t = 0; t < 8; t++) {
                    uint32_t bf[2];
                    bf[0] = __float_as_uint(Vs[(k0 + tq    ) * FP + on0 + t * 8 + g]);
                    bf[1] = __float_as_uint(Vs[(k0 + tq + 4) * FP + on0 + t * 8 + g]);
                    mma_tf32(oc[t], a, bf);
                }
            }
        }
    }
    __syncthreads();

    {
        const int on0 = wc * 64;
        const float inv_lo = 1.0f / lrow[sr + g];
        const float inv_hi = 1.0f / lrow[sr + g + 8];
        float* Obase = g_attn + ((size_t)b * SEQ + qt * 64) * DM + h * DH;
        #pragma unroll
        for (int t = 0; t < 8; t++) {
            const int col = on0 + t * 8 + 2 * tq;
            float2 lo = make_float2(wmma::__float_to_tf32(oc[t][0] * inv_lo),
                                    wmma::__float_to_tf32(oc[t][1] * inv_lo));
            float2 hi = make_float2(wmma::__float_to_tf32(oc[t][2] * inv_hi),
                                    wmma::__float_to_tf32(oc[t][3] * inv_hi));
            *(float2*)(Obase + (size_t)(sr + g    ) * DM + col) = lo;
            *(float2*)(Obase + (size_t)(sr + g + 8) * DM + col) = hi;
        }
    }
}

// ---------------------------------------------------------------------------
extern "C" void kernel_launch(void* const* d_in, const int* in_sizes, int n_in,
                              void* d_out, int out_size)
{
    const float* x    = (const float*)d_in[0];
    const float* Wqkv = (const float*)d_in[1];
    const float* bqkv = (const float*)d_in[2];
    const float* Wout = (const float*)d_in[3];
    const float* bout = (const float*)d_in[4];
    float* out = (float*)d_out;

    const int M = BATCH * SEQ;

    cudaFuncSetAttribute(gemm_ldsm_kernel,
                         cudaFuncAttributeMaxDynamicSharedMemorySize, LGEMM_SMEM);
    cudaFuncSetAttribute(gemm_wmma_kernel,
                         cudaFuncAttributeMaxDynamicSharedMemorySize, WGEMM_SMEM);
    cudaFuncSetAttribute(flash_kernel,
                         cudaFuncAttributeMaxDynamicSharedMemorySize, FLASH_SMEM);

    float* xt; float* wq; float* wo;
    cudaGetSymbolAddress((void**)&xt, g_xt);
    cudaGetSymbolAddress((void**)&wq, g_wq);
    cudaGetSymbolAddress((void**)&wo, g_wo);

    // 0) pre-pass
    cvt_tf32_kernel<<<(int)((size_t)BATCH*SEQ*DM/4/256), 256>>>(x, xt, (int)((size_t)BATCH*SEQ*DM/4));
    {
        dim3 blk(32, 8);
        transpose_tf32_kernel<<<dim3((3*DM)/32, DM/32), blk>>>(Wqkv, wq, DM, 3*DM);
    }
    cvt_tf32_kernel<<<(int)((size_t)DM*DM/4/256), 256>>>(Wout, wo, (int)((size_t)DM*DM/4));

    // 1) QKV projection (ldmatrix + raw mma)
    {
        dim3 grid((3 * DM) / 128, M / 128);
        gemm_ldsm_kernel<<<grid, 256, LGEMM_SMEM>>>(xt, wq, bqkv, M, 3 * DM, DM);
    }
    // 2) flash attention v4 (ldmatrix K/P feeds)
    {
        dim3 grid(SEQ / 64, NH, BATCH);
        flash_kernel<<<grid, 256, FLASH_SMEM>>>();
    }
    // 3) output projection (wmma) -> d_out
    {
        dim3 grid(DM / 128, M / 128);
        gemm_wmma_kernel<<<grid, 256, WGEMM_SMEM>>>(wo, bout, out, M, DM, DM);
    }
}

// round 11
// speedup vs baseline: 1.3744x; 1.0024x over previous
#include <cuda_runtime.h>
#include <mma.h>
#include <math.h>
#include <stdint.h>

using namespace nvcuda;

#define BATCH 2
#define SEQ   2048
#define NH    16
#define DH    128
#define DM    2048
#define NQ    ((size_t)BATCH*NH*SEQ*DH)

__device__ float g_qkv[3*(size_t)BATCH*NH*SEQ*DH];
__device__ float g_attn[(size_t)BATCH*SEQ*DM];
__device__ float g_xt[(size_t)BATCH*SEQ*DM];
__device__ float g_wq[(size_t)DM*3*DM];   // W_qkv^T [6144][2048] tf32 (ldsm gemm)
__device__ float g_wo[(size_t)DM*DM];     // W_out   [2048][2048] tf32 (wmma gemm)

// ---------------------------------------------------------------------------
__device__ __forceinline__ uint32_t smem_u32(const void* p) {
    return (uint32_t)__cvta_generic_to_shared(p);
}
#define CP_ASYNC16(dst_u32, src_ptr) \
    asm volatile("cp.async.cg.shared.global [%0], [%1], 16;" :: "r"(dst_u32), "l"(src_ptr))
#define CP_COMMIT()   asm volatile("cp.async.commit_group;")
#define CP_WAIT(n)    asm volatile("cp.async.wait_group %0;" :: "n"(n))

// m16n8k8 tf32 mma, D += A*B
__device__ __forceinline__ void mma_tf32(float* d, const uint32_t* a, const uint32_t* b) {
    asm volatile(
        "mma.sync.aligned.m16n8k8.row.col.f32.tf32.tf32.f32 "
        "{%0,%1,%2,%3},{%4,%5,%6,%7},{%8,%9},{%0,%1,%2,%3};"
        : "+f"(d[0]), "+f"(d[1]), "+f"(d[2]), "+f"(d[3])
        : "r"(a[0]), "r"(a[1]), "r"(a[2]), "r"(a[3]), "r"(b[0]), "r"(b[1]));
}

// ldmatrix x4
__device__ __forceinline__ void ldsm4(uint32_t* r, uint32_t addr) {
    asm volatile("ldmatrix.sync.aligned.m8n8.x4.shared.b16 {%0,%1,%2,%3}, [%4];"
        : "=r"(r[0]), "=r"(r[1]), "=r"(r[2]), "=r"(r[3]) : "r"(addr));
}

// ---------------------------------------------------------------------------
// pre-passes
// ---------------------------------------------------------------------------
__global__ void cvt_tf32_kernel(const float* __restrict__ in,
                                float* __restrict__ out, int n4)
{
    int i = blockIdx.x * blockDim.x + threadIdx.x;
    if (i < n4) {
        float4 v = ((const float4*)in)[i];
        v.x = wmma::__float_to_tf32(v.x); v.y = wmma::__float_to_tf32(v.y);
        v.z = wmma::__float_to_tf32(v.z); v.w = wmma::__float_to_tf32(v.w);
        ((float4*)out)[i] = v;
    }
}

__global__ void transpose_tf32_kernel(const float* __restrict__ in,
                                      float* __restrict__ out, int R, int C)
{
    __shared__ float t[32][33];
    const int c0 = blockIdx.x * 32, r0 = blockIdx.y * 32;
    #pragma unroll
    for (int i = 0; i < 32; i += 8)
        t[threadIdx.y + i][threadIdx.x] =
            in[(size_t)(r0 + threadIdx.y + i) * C + c0 + threadIdx.x];
    __syncthreads();
    #pragma unroll
    for (int i = 0; i < 32; i += 8)
        out[(size_t)(c0 + threadIdx.y + i) * R + r0 + threadIdx.x] =
            wmma::__float_to_tf32(t[threadIdx.x][threadIdx.y + i]);
}

// ---------------------------------------------------------------------------
// QKV GEMM: raw m16n8k8 + ldmatrix feed (round-8/9 proven, unchanged).
// ---------------------------------------------------------------------------
#define GP 36
#define LSTAGE_F (2*128*GP)
#define LSTAGE_B (LSTAGE_F*4)
#define A_BYTES  (128*GP*4)
#define CS_PITCH 132
#define LGEMM_SMEM (3*LSTAGE_B)   // 110592 B

__global__ __launch_bounds__(256, 2)
void gemm_ldsm_kernel(const float* __restrict__ Aglob, const float* __restrict__ Bt,
                      const float* __restrict__ bias,
                      int M, int N, int K)
{
    extern __shared__ float sm[];
    float* Cs = sm;

    const int tid  = threadIdx.x;
    const int warp = tid >> 5, lane = tid & 31;
    const int wr   = warp >> 1;
    const int wc   = warp & 1;
    const int g    = lane >> 2, tq = lane & 3;
    const int rowBlock = blockIdx.y * 128;
    const int colBlock = blockIdx.x * 128;

    const int ldRow  = tid >> 1;
    const int ldHalf = (tid & 1) * 16;
    const float* Asrc = Aglob + (size_t)(rowBlock + ldRow) * K + ldHalf;
    const float* Bsrc = Bt + (size_t)(colBlock + ldRow) * K + ldHalf;

    const uint32_t smBase = smem_u32(sm);
    const uint32_t ldOff  = (uint32_t)((ldRow * GP + ldHalf) * 4);

    uint32_t aOff[2];
    #pragma unroll
    for (int mi = 0; mi < 2; mi++)
        aOff[mi] = (uint32_t)(((wr * 32 + mi * 16 + (lane & 15)) * GP + (lane >> 4) * 4) * 4);
    uint32_t bOff[4];
    #pragma unroll
    for (int p = 0; p < 4; p++)
        bOff[p] = (uint32_t)(A_BYTES +
                  ((wc * 64 + p * 16 + (lane & 7) + ((lane >> 4) << 3)) * GP
                   + ((lane >> 3) & 1) * 4) * 4);

    float acc[2][8][4] = {};
    const int NIT = K >> 5;

    auto issue = [&](int tt, int s) {
        const int k0 = tt << 5;
        const uint32_t sb = smBase + (uint32_t)s * LSTAGE_B;
        #pragma unroll
        for (int i = 0; i < 4; i++)
            CP_ASYNC16(sb + ldOff + (uint32_t)(i * 16), Asrc + k0 + i * 4);
        #pragma unroll
        for (int i = 0; i < 4; i++)
            CP_ASYNC16(sb + (uint32_t)A_BYTES + ldOff + (uint32_t)(i * 16), Bsrc + k0 + i * 4);
        CP_COMMIT();
    };

    issue(0, 0);

    for (int t = 0; t < NIT; t++) {
        if (t + 1 < NIT) {
            issue(t + 1, (t + 1) % 3);
            CP_WAIT(1);
        } else {
            CP_WAIT(0);
        }
        __syncthreads();

        const uint32_t sb = smBase + (uint32_t)(t % 3) * LSTAGE_B;
        #pragma unroll
        for (int ks = 0; ks < 4; ks++) {
            const uint32_t kb = (uint32_t)(ks * 32);
            uint32_t a0[4], a1[4];
            ldsm4(a0, sb + aOff[0] + kb);
            ldsm4(a1, sb + aOff[1] + kb);
            #pragma unroll
            for (int p = 0; p < 4; p++) {
                uint32_t bb[4];
                ldsm4(bb, sb + bOff[p] + kb);
                mma_tf32(acc[0][2*p  ], a0, bb);
                mma_tf32(acc[0][2*p+1], a0, bb + 2);
                mma_tf32(acc[1][2*p  ], a1, bb);
                mma_tf32(acc[1][2*p+1], a1, bb + 2);
            }
        }
    }
    __syncthreads();

    #pragma unroll
    for (int mi = 0; mi < 2; mi++) {
        const int r_lo = wr * 32 + mi * 16 + g;
        #pragma unroll
        for (int j = 0; j < 8; j++) {
            const int col = wc * 64 + j * 8 + 2 * tq;
            *(float2*)&Cs[r_lo * CS_PITCH + col] =
                make_float2(acc[mi][j][0], acc[mi][j][1]);
            *(float2*)&Cs[(r_lo + 8) * CS_PITCH + col] =
                make_float2(acc[mi][j][2], acc[mi][j][3]);
        }
    }
    __syncthreads();

    #pragma unroll
    for (int it = 0; it < 16; it++) {
        int u = tid + it * 256;
        int row = u >> 5, c4 = (u & 31) * 4;
        float4 v = *(float4*)&Cs[row * CS_PITCH + c4];
        const int gcol = colBlock + c4;
        v.x += bias[gcol + 0]; v.y += bias[gcol + 1];
        v.z += bias[gcol + 2]; v.w += bias[gcol + 3];
        const int gr = rowBlock + row;
        v.x = wmma::__float_to_tf32(v.x); v.y = wmma::__float_to_tf32(v.y);
        v.z = wmma::__float_to_tf32(v.z); v.w = wmma::__float_to_tf32(v.w);
        const int part = gcol >> 11;
        const int c2   = gcol & 2047;
        const int h    = c2 >> 7;
        const int d0   = c2 & 127;
        const int bb   = gr >> 11;
        const int s    = gr & 2047;
        float* dst = g_qkv + (size_t)part * NQ
                   + (((size_t)(bb * NH + h) * SEQ) + s) * DH + d0;
        *(float4*)dst = v;
    }
}

// ---------------------------------------------------------------------------
// Out-projection GEMM: wmma 3-stage (round-7/9 proven, unchanged).
// ---------------------------------------------------------------------------
#define WAS_PITCH 36
#define WBS_PITCH 132
#define WSTAGE_F  (128*WAS_PITCH + 32*WBS_PITCH)
#define WGEMM_SMEM (3*WSTAGE_F*4)   // 105984 B

__global__ __launch_bounds__(256, 2)
void gemm_wmma_kernel(const float* __restrict__ B,
                      const float* __restrict__ bias, float* __restrict__ C,
                      int M, int N, int K)
{
    extern __shared__ float sm[];
    float* Cs = sm;

    const float* Abase = (const float*)g_attn;

    const int tid  = threadIdx.x;
    const int warp = tid >> 5;
    const int wr   = warp >> 1;
    const int wc   = warp & 1;
    const int rowBlock = blockIdx.y * 128;
    const int colBlock = blockIdx.x * 128;

    const int aRow0 = tid >> 3;
    const int aCol  = (tid & 7) * 4;
    const int bRow0 = tid >> 5;
    const int bCol  = (tid & 31) * 4;

    const float* Asrc = Abase + (size_t)(rowBlock + aRow0) * K + aCol;
    const float* Bsrc = B + (size_t)bRow0 * N + colBlock + bCol;

    const uint32_t smBase = smem_u32(sm);
    const uint32_t aOffB  = (uint32_t)((aRow0 * WAS_PITCH + aCol) * 4);
    const uint32_t bOffB  = (uint32_t)((128 * WAS_PITCH + bRow0 * WBS_PITCH + bCol) * 4);

    wmma::fragment<wmma::accumulator, 16, 16, 8, float> acc[2][4];
    #pragma unroll
    for (int i = 0; i < 2; i++)
        #pragma unroll
        for (int j = 0; j < 4; j++)
            wmma::fill_fragment(acc[i][j], 0.0f);

    const int NIT = K >> 5;

    auto issue = [&](int tt, int s) {
        const int k0 = tt << 5;
        const uint32_t sb = smBase + (uint32_t)s * (WSTAGE_F * 4);
        #pragma unroll
        for (int it = 0; it < 4; it++)
            CP_ASYNC16(sb + aOffB + (uint32_t)(it * 32 * WAS_PITCH * 4),
                       Asrc + (size_t)(it * 32) * K + k0);
        #pragma unroll
        for (int it = 0; it < 4; it++)
            CP_ASYNC16(sb + bOffB + (uint32_t)(it * 8 * WBS_PITCH * 4),
                       Bsrc + (size_t)(k0 + it * 8) * N);
        CP_COMMIT();
    };

    issue(0, 0);

    for (int t = 0; t < NIT; t++) {
        if (t + 1 < NIT) {
            issue(t + 1, (t + 1) % 3);
            CP_WAIT(1);
        } else {
            CP_WAIT(0);
        }
        __syncthreads();

        const float* As = sm + (t % 3) * WSTAGE_F;
        const float* Bs = As + 128 * WAS_PITCH;
        #pragma unroll
        for (int ks = 0; ks < 4; ks++) {
            wmma::fragment<wmma::matrix_a, 16, 16, 8, wmma::precision::tf32, wmma::row_major> af[2];
            wmma::fragment<wmma::matrix_b, 16, 16, 8, wmma::precision::tf32, wmma::row_major> bf[4];
            #pragma unroll
            for (int i = 0; i < 2; i++)
                wmma::load_matrix_sync(af[i], &As[(wr * 32 + i * 16) * WAS_PITCH + ks * 8], WAS_PITCH);
            #pragma unroll
            for (int j = 0; j < 4; j++)
                wmma::load_matrix_sync(bf[j], &Bs[(ks * 8) * WBS_PITCH + wc * 64 + j * 16], WBS_PITCH);
            #pragma unroll
            for (int i = 0; i < 2; i++)
                #pragma unroll
                for (int j = 0; j < 4; j++)
                    wmma::mma_sync(acc[i][j], af[i], bf[j], acc[i][j]);
        }
    }
    __syncthreads();

    #pragma unroll
    for (int i = 0; i < 2; i++)
        #pragma unroll
        for (int j = 0; j < 4; j++)
            wmma::store_matrix_sync(&Cs[(wr * 32 + i * 16) * CS_PITCH + wc * 64 + j * 16],
                                    acc[i][j], CS_PITCH, wmma::mem_row_major);
    __syncthreads();

    #pragma unroll
    for (int it = 0; it < 16; it++) {
        int u = tid + it * 256;
        int row = u >> 5, c4 = (u & 31) * 4;
        float4 v = *(float4*)&Cs[row * CS_PITCH + c4];
        const int gcol = colBlock + c4;
        v.x += bias[gcol + 0]; v.y += bias[gcol + 1];
        v.z += bias[gcol + 2]; v.w += bias[gcol + 3];
        const int gr = rowBlock + row;
        *(float4*)(C + (size_t)gr * N + gcol) = v;
    }
}

// ---------------------------------------------------------------------------
// Causal flash attention v5: 128-query tile, 512 threads (16 warps, 8x2),
// 2-stage cp.async KV ring (64-key tiles), Q register-resident,
// ldmatrix K/P feeds. Big-qt-first scheduling.
// smem: 2 stages x (K[64][132] + V[64][132]) = 135168 B, Ss[128][68],
//       stats 3x128. Total 171520 B -> 1 CTA/SM.
// ---------------------------------------------------------------------------
#define FP 132
#define SP 68
#define KVSTRIDE (2*8448)
#define FLASH_SMEM ((4*8448 + 128*SP + 3*128) * 4)   // 171520 B

__global__ __launch_bounds__(512)
void flash_kernel()
{
    extern __shared__ float smf[];
    float* Ss   = smf + 4 * 8448;
    float* mrow = Ss + 128 * SP;
    float* lrow = mrow + 128;
    float* arow = lrow + 128;

    const int qt = (int)(gridDim.x - 1) - (int)blockIdx.x;   // big tiles first
    const int h = blockIdx.y, b = blockIdx.z;
    const int bh = b * NH + h;

    const float* Qp = g_qkv + 0 * NQ + ((size_t)bh * SEQ + qt * 128) * DH;
    const float* Kp = g_qkv + 1 * NQ + (size_t)bh * SEQ * DH;
    const float* Vp = g_qkv + 2 * NQ + (size_t)bh * SEQ * DH;

    const int tid  = threadIdx.x;
    const int warp = tid >> 5, lane = tid & 31;
    const int wr = warp >> 1, wc = warp & 1;      // wr 0..7, wc 0..1
    const int g  = lane >> 2, tq = lane & 3;
    const int sr = wr * 16;                       // S row band 0..112

    const float scale = 0.08838834764831845f;

    // ldmatrix lane offsets
    const uint32_t kOff0 = (uint32_t)(((wc * 32 + (lane & 7) + ((lane >> 4) << 3)) * FP
                                      + ((lane >> 3) & 1) * 4) * 4);
    const uint32_t kOff1 = kOff0 + (uint32_t)(16 * FP * 4);
    const uint32_t pOff  = (uint32_t)(((sr + (lane & 15)) * SP + (lane >> 4) * 4) * 4);
    const uint32_t ssB   = smem_u32(Ss);

    auto issueKV = [&](int kt, int s) {
        const float* Kt = Kp + (size_t)kt * 64 * DH;
        const float* Vt = Vp + (size_t)kt * 64 * DH;
        float* Kd = smf + s * KVSTRIDE;
        float* Vd = Kd + 8448;
        #pragma unroll
        for (int it = 0; it < 4; it++) {
            int u = tid + it * 512;
            int r = u >> 5, c = (u & 31) * 4;
            CP_ASYNC16(smem_u32(&Kd[r * FP + c]), Kt + r * DH + c);
            CP_ASYNC16(smem_u32(&Vd[r * FP + c]), Vt + r * DH + c);
        }
        CP_COMMIT();
    };

    issueKV(0, 0);
    // stage Q (128x128) into stage-1 region, then pull to registers
    {
        float* Qtmp = smf + KVSTRIDE;
        #pragma unroll
        for (int it = 0; it < 8; it++) {
            int u = tid + it * 512;
            int r = u >> 5, c = (u & 31) * 4;
            *(float4*)&Qtmp[r * FP + c] = *(const float4*)(Qp + r * DH + c);
        }
    }
    if (tid < 128) { mrow[tid] = -1e30f; lrow[tid] = 0.f; }
    __syncthreads();

    uint32_t qf[16][4];
    {
        const float* Qtmp = smf + KVSTRIDE;
        #pragma unroll
        for (int ks = 0; ks < 16; ks++) {
            const int k0 = ks * 8;
            qf[ks][0] = __float_as_uint(Qtmp[(sr + g    ) * FP + k0 + tq    ]);
            qf[ks][1] = __float_as_uint(Qtmp[(sr + g + 8) * FP + k0 + tq    ]);
            qf[ks][2] = __float_as_uint(Qtmp[(sr + g    ) * FP + k0 + tq + 4]);
            qf[ks][3] = __float_as_uint(Qtmp[(sr + g + 8) * FP + k0 + tq + 4]);
        }
    }
    __syncthreads();   // qf read done before issueKV(1,1) overwrites stage 1

    float oc[8][4];
    #pragma unroll
    for (int t = 0; t < 8; t++)
        #pragma unroll
        for (int i = 0; i < 4; i++) oc[t][i] = 0.f;

    const int ktMax = 2 * qt + 1;
    for (int kt = 0; kt <= ktMax; kt++) {
        const int buf = kt & 1;
        const float* Ks = smf + buf * KVSTRIDE;
        const float* Vs = Ks + 8448;

        if (kt < ktMax) {
            issueKV(kt + 1, buf ^ 1);
            CP_WAIT(1);
        } else {
            CP_WAIT(0);
        }
        __syncthreads();                     // [B] KV(kt) visible

        // ---- S = Q K^T : Q regs, K via ldmatrix; warp 16x32 ----
        {
            float sc[4][4] = {};
            const uint32_t kBase = smem_u32(Ks);
            #pragma unroll
            for (int ks = 0; ks < 16; ks++) {
                const uint32_t kb = (uint32_t)(ks * 32);
                uint32_t b0[4], b1[4];
                ldsm4(b0, kBase + kOff0 + kb);
                ldsm4(b1, kBase + kOff1 + kb);
                mma_tf32(sc[0], qf[ks], b0);
                mma_tf32(sc[1], qf[ks], b0 + 2);
                mma_tf32(sc[2], qf[ks], b1);
                mma_tf32(sc[3], qf[ks], b1 + 2);
            }
            const int sn0 = wc * 32;
            #pragma unroll
            for (int t = 0; t < 4; t++) {
                *(float2*)&Ss[(sr + g    ) * SP + sn0 + t * 8 + 2 * tq] =
                    make_float2(sc[t][0], sc[t][1]);
                *(float2*)&Ss[(sr + g + 8) * SP + sn0 + t * 8 + 2 * tq] =
                    make_float2(sc[t][2], sc[t][3]);
            }
        }
        __syncthreads();                     // [C]

        // ---- softmax (fp32): 4 lanes/row, 128 rows ----
        {
            const int row = tid >> 2;        // 0..127
            const int q4  = tid & 3;
            const int c0  = q4 * 16;
            const bool diag = (kt >= 2 * qt);
            const int qrow = qt * 128 + row;
            const int kc0  = kt * 64 + c0;
            float s[16];
            #pragma unroll
            for (int j = 0; j < 16; j++) {
                float v = Ss[row * SP + c0 + j] * scale;
                if (diag && (kc0 + j) > qrow) v = -1e30f;
                s[j] = v;
            }
            float mt = s[0];
            #pragma unroll
            for (int j = 1; j < 16; j++) mt = fmaxf(mt, s[j]);
            mt = fmaxf(mt, __shfl_xor_sync(0xffffffffu, mt, 1));
            mt = fmaxf(mt, __shfl_xor_sync(0xffffffffu, mt, 2));
            const float m_old = mrow[row];
            const float mnew  = fmaxf(m_old, mt);
            const float alpha = __expf(m_old - mnew);
            float rs = 0.f;
            #pragma unroll
            for (int j = 0; j < 16; j++) {
                float p = __expf(s[j] - mnew);
                rs += p;
                Ss[row * SP + c0 + j] = wmma::__float_to_tf32(p);
            }
            rs += __shfl_xor_sync(0xffffffffu, rs, 1);
            rs += __shfl_xor_sync(0xffffffffu, rs, 2);
            if (q4 == 0) {
                lrow[row] = lrow[row] * alpha + rs;
                mrow[row] = mnew;
                arow[row] = alpha;
            }
        }
        __syncthreads();                     // [D]

        // ---- O = O*alpha + P V : P via ldmatrix, V scalar; warp 16x64 ----
        {
            const float a_lo = arow[sr + g], a_hi = arow[sr + g + 8];
            #pragma unroll
            for (int t = 0; t < 8; t++) {
                oc[t][0] *= a_lo; oc[t][1] *= a_lo;
                oc[t][2] *= a_hi; oc[t][3] *= a_hi;
            }
            const int on0 = wc * 64;
            #pragma unroll
            for (int ks = 0; ks < 8; ks++) {
                const int k0 = ks * 8;
                uint32_t a[4];
                ldsm4(a, ssB + pOff + (uint32_t)(ks * 32));
                #pragma unroll
                for (int t = 0; t < 8; t++) {
                    uint32_t bf[2];
                    bf[0] = __float_as_uint(Vs[(k0 + tq    ) * FP + on0 + t * 8 + g]);
                    bf[1] = __float_as_uint(Vs[(k0 + tq + 4) * FP + on0 + t * 8 + g]);
                    mma_tf32(oc[t], a, bf);
                }
            }
        }
        __syncthreads();                     // [A] V reads done -> buf reusable
    }

    // epilogue: g_attn = tf32(O / l)
    {
        const int on0 = wc * 64;
        const float inv_lo = 1.0f / lrow[sr + g];
        const float inv_hi = 1.0f / lrow[sr + g + 8];
        float* Obase = g_attn + ((size_t)b * SEQ + qt * 128) * DM + h * DH;
        #pragma unroll
        for (int t = 0; t < 8; t++) {
            const int col = on0 + t * 8 + 2 * tq;
            float2 lo = make_float2(wmma::__float_to_tf32(oc[t][0] * inv_lo),
                                    wmma::__float_to_tf32(oc[t][1] * inv_lo));
            float2 hi = make_float2(wmma::__float_to_tf32(oc[t][2] * inv_hi),
                                    wmma::__float_to_tf32(oc[t][3] * inv_hi));
            *(float2*)(Obase + (size_t)(sr + g    ) * DM + col) = lo;
            *(float2*)(Obase + (size_t)(sr + g + 8) * DM + col) = hi;
        }
    }
}

// ---------------------------------------------------------------------------
extern "C" void kernel_launch(void* const* d_in, const int* in_sizes, int n_in,
                              void* d_out, int out_size)
{
    const float* x    = (const float*)d_in[0];
    const float* Wqkv = (const float*)d_in[1];
    const float* bqkv = (const float*)d_in[2];
    const float* Wout = (const float*)d_in[3];
    const float* bout = (const float*)d_in[4];
    float* out = (float*)d_out;

    const int M = BATCH * SEQ;

    cudaFuncSetAttribute(gemm_ldsm_kernel,
                         cudaFuncAttributeMaxDynamicSharedMemorySize, LGEMM_SMEM);
    cudaFuncSetAttribute(gemm_wmma_kernel,
                         cudaFuncAttributeMaxDynamicSharedMemorySize, WGEMM_SMEM);
    cudaFuncSetAttribute(flash_kernel,
                         cudaFuncAttributeMaxDynamicSharedMemorySize, FLASH_SMEM);

    float* xt; float* wq; float* wo;
    cudaGetSymbolAddress((void**)&xt, g_xt);
    cudaGetSymbolAddress((void**)&wq, g_wq);
    cudaGetSymbolAddress((void**)&wo, g_wo);

    // 0) pre-pass
    cvt_tf32_kernel<<<(int)((size_t)BATCH*SEQ*DM/4/256), 256>>>(x, xt, (int)((size_t)BATCH*SEQ*DM/4));
    {
        dim3 blk(32, 8);
        transpose_tf32_kernel<<<dim3((3*DM)/32, DM/32), blk>>>(Wqkv, wq, DM, 3*DM);
    }
    cvt_tf32_kernel<<<(int)((size_t)DM*DM/4/256), 256>>>(Wout, wo, (int)((size_t)DM*DM/4));

    // 1) QKV projection (ldmatrix + raw mma)
    {
        dim3 grid((3 * DM) / 128, M / 128);
        gemm_ldsm_kernel<<<grid, 256, LGEMM_SMEM>>>(xt, wq, bqkv, M, 3 * DM, DM);
    }
    // 2) flash attention v5 (128-q tile, 512 threads)
    {
        dim3 grid(SEQ / 128, NH, BATCH);
        flash_kernel<<<grid, 512, FLASH_SMEM>>>();
    }
    // 3) output projection (wmma) -> d_out
    {
        dim3 grid(DM / 128, M / 128);
        gemm_wmma_kernel<<<grid, 256, WGEMM_SMEM>>>(wo, bout, out, M, DM, DM);
    }
}

// round 12
// speedup vs baseline: 1.4133x; 1.0283x over previous
#include <cuda_runtime.h>
#include <mma.h>
#include <math.h>
#include <stdint.h>

using namespace nvcuda;

#define BATCH 2
#define SEQ   2048
#define NH    16
#define DH    128
#define DM    2048
#define NQ    ((size_t)BATCH*NH*SEQ*DH)

// g_qkv layout: part 0 (Q), part 1 (K): [b,h,seq,d]. part 2 (V): [b,h,d,seq] (TRANSPOSED)
__device__ float g_qkv[3*(size_t)BATCH*NH*SEQ*DH];
__device__ float g_attn[(size_t)BATCH*SEQ*DM];
__device__ float g_xt[(size_t)BATCH*SEQ*DM];
__device__ float g_wq[(size_t)DM*3*DM];   // W_qkv^T [6144][2048] tf32
__device__ float g_wo[(size_t)DM*DM];     // W_out   [2048][2048] tf32

// ---------------------------------------------------------------------------
__device__ __forceinline__ uint32_t smem_u32(const void* p) {
    return (uint32_t)__cvta_generic_to_shared(p);
}
#define CP_ASYNC16(dst_u32, src_ptr) \
    asm volatile("cp.async.cg.shared.global [%0], [%1], 16;" :: "r"(dst_u32), "l"(src_ptr))
#define CP_COMMIT()   asm volatile("cp.async.commit_group;")
#define CP_WAIT(n)    asm volatile("cp.async.wait_group %0;" :: "n"(n))

__device__ __forceinline__ void mma_tf32(float* d, const uint32_t* a, const uint32_t* b) {
    asm volatile(
        "mma.sync.aligned.m16n8k8.row.col.f32.tf32.tf32.f32 "
        "{%0,%1,%2,%3},{%4,%5,%6,%7},{%8,%9},{%0,%1,%2,%3};"
        : "+f"(d[0]), "+f"(d[1]), "+f"(d[2]), "+f"(d[3])
        : "r"(a[0]), "r"(a[1]), "r"(a[2]), "r"(a[3]), "r"(b[0]), "r"(b[1]));
}

__device__ __forceinline__ void ldsm4(uint32_t* r, uint32_t addr) {
    asm volatile("ldmatrix.sync.aligned.m8n8.x4.shared.b16 {%0,%1,%2,%3}, [%4];"
        : "=r"(r[0]), "=r"(r[1]), "=r"(r[2]), "=r"(r[3]) : "r"(addr));
}

// ---------------------------------------------------------------------------
// pre-passes
// ---------------------------------------------------------------------------
__global__ void cvt_tf32_kernel(const float* __restrict__ in,
                                float* __restrict__ out, int n4)
{
    int i = blockIdx.x * blockDim.x + threadIdx.x;
    if (i < n4) {
        float4 v = ((const float4*)in)[i];
        v.x = wmma::__float_to_tf32(v.x); v.y = wmma::__float_to_tf32(v.y);
        v.z = wmma::__float_to_tf32(v.z); v.w = wmma::__float_to_tf32(v.w);
        ((float4*)out)[i] = v;
    }
}

__global__ void transpose_tf32_kernel(const float* __restrict__ in,
                                      float* __restrict__ out, int R, int C)
{
    __shared__ float t[32][33];
    const int c0 = blockIdx.x * 32, r0 = blockIdx.y * 32;
    #pragma unroll
    for (int i = 0; i < 32; i += 8)
        t[threadIdx.y + i][threadIdx.x] =
            in[(size_t)(r0 + threadIdx.y + i) * C + c0 + threadIdx.x];
    __syncthreads();
    #pragma unroll
    for (int i = 0; i < 32; i += 8)
        out[(size_t)(c0 + threadIdx.y + i) * R + r0 + threadIdx.x] =
            wmma::__float_to_tf32(t[threadIdx.x][threadIdx.y + i]);
}

// ---------------------------------------------------------------------------
// QKV GEMM: raw m16n8k8 + ldmatrix feed. V part stored TRANSPOSED.
// ---------------------------------------------------------------------------
#define GP 36
#define LSTAGE_F (2*128*GP)
#define LSTAGE_B (LSTAGE_F*4)
#define A_BYTES  (128*GP*4)
#define CS_PITCH 132
#define LGEMM_SMEM (3*LSTAGE_B)   // 110592 B

__global__ __launch_bounds__(256, 2)
void gemm_ldsm_kernel(const float* __restrict__ Aglob, const float* __restrict__ Bt,
                      const float* __restrict__ bias,
                      int M, int N, int K)
{
    extern __shared__ float sm[];
    float* Cs = sm;

    const int tid  = threadIdx.x;
    const int warp = tid >> 5, lane = tid & 31;
    const int wr   = warp >> 1;
    const int wc   = warp & 1;
    const int g    = lane >> 2, tq = lane & 3;
    const int rowBlock = blockIdx.y * 128;
    const int colBlock = blockIdx.x * 128;

    const int ldRow  = tid >> 1;
    const int ldHalf = (tid & 1) * 16;
    const float* Asrc = Aglob + (size_t)(rowBlock + ldRow) * K + ldHalf;
    const float* Bsrc = Bt + (size_t)(colBlock + ldRow) * K + ldHalf;

    const uint32_t smBase = smem_u32(sm);
    const uint32_t ldOff  = (uint32_t)((ldRow * GP + ldHalf) * 4);

    uint32_t aOff[2];
    #pragma unroll
    for (int mi = 0; mi < 2; mi++)
        aOff[mi] = (uint32_t)(((wr * 32 + mi * 16 + (lane & 15)) * GP + (lane >> 4) * 4) * 4);
    uint32_t bOff[4];
    #pragma unroll
    for (int p = 0; p < 4; p++)
        bOff[p] = (uint32_t)(A_BYTES +
                  ((wc * 64 + p * 16 + (lane & 7) + ((lane >> 4) << 3)) * GP
                   + ((lane >> 3) & 1) * 4) * 4);

    float acc[2][8][4] = {};
    const int NIT = K >> 5;

    auto issue = [&](int tt, int s) {
        const int k0 = tt << 5;
        const uint32_t sb = smBase + (uint32_t)s * LSTAGE_B;
        #pragma unroll
        for (int i = 0; i < 4; i++)
            CP_ASYNC16(sb + ldOff + (uint32_t)(i * 16), Asrc + k0 + i * 4);
        #pragma unroll
        for (int i = 0; i < 4; i++)
            CP_ASYNC16(sb + (uint32_t)A_BYTES + ldOff + (uint32_t)(i * 16), Bsrc + k0 + i * 4);
        CP_COMMIT();
    };

    issue(0, 0);

    for (int t = 0; t < NIT; t++) {
        if (t + 1 < NIT) {
            issue(t + 1, (t + 1) % 3);
            CP_WAIT(1);
        } else {
            CP_WAIT(0);
        }
        __syncthreads();

        const uint32_t sb = smBase + (uint32_t)(t % 3) * LSTAGE_B;
        #pragma unroll
        for (int ks = 0; ks < 4; ks++) {
            const uint32_t kb = (uint32_t)(ks * 32);
            uint32_t a0[4], a1[4];
            ldsm4(a0, sb + aOff[0] + kb);
            ldsm4(a1, sb + aOff[1] + kb);
            #pragma unroll
            for (int p = 0; p < 4; p++) {
                uint32_t bb[4];
                ldsm4(bb, sb + bOff[p] + kb);
                mma_tf32(acc[0][2*p  ], a0, bb);
                mma_tf32(acc[0][2*p+1], a0, bb + 2);
                mma_tf32(acc[1][2*p  ], a1, bb);
                mma_tf32(acc[1][2*p+1], a1, bb + 2);
            }
        }
    }
    __syncthreads();

    #pragma unroll
    for (int mi = 0; mi < 2; mi++) {
        const int r_lo = wr * 32 + mi * 16 + g;
        #pragma unroll
        for (int j = 0; j < 8; j++) {
            const int col = wc * 64 + j * 8 + 2 * tq;
            *(float2*)&Cs[r_lo * CS_PITCH + col] =
                make_float2(acc[mi][j][0], acc[mi][j][1]);
            *(float2*)&Cs[(r_lo + 8) * CS_PITCH + col] =
                make_float2(acc[mi][j][2], acc[mi][j][3]);
        }
    }
    __syncthreads();

    #pragma unroll
    for (int it = 0; it < 16; it++) {
        int u = tid + it * 256;
        int row = u >> 5, c4 = (u & 31) * 4;
        float4 v = *(float4*)&Cs[row * CS_PITCH + c4];
        const int gcol = colBlock + c4;
        v.x += bias[gcol + 0]; v.y += bias[gcol + 1];
        v.z += bias[gcol + 2]; v.w += bias[gcol + 3];
        const int gr = rowBlock + row;
        v.x = wmma::__float_to_tf32(v.x); v.y = wmma::__float_to_tf32(v.y);
        v.z = wmma::__float_to_tf32(v.z); v.w = wmma::__float_to_tf32(v.w);
        const int part = gcol >> 11;
        const int c2   = gcol & 2047;
        const int h    = c2 >> 7;
        const int d0   = c2 & 127;
        const int bb   = gr >> 11;
        const int s    = gr & 2047;
        if (part == 2) {
            // V stored transposed: [b,h,d,s]
            float* dstv = g_qkv + 2 * NQ
                        + (((size_t)(bb * NH + h)) * DH + d0) * SEQ + s;
            dstv[0 * SEQ] = v.x;
            dstv[1 * SEQ] = v.y;
            dstv[2 * SEQ] = v.z;
            dstv[3 * SEQ] = v.w;
        } else {
            float* dst = g_qkv + (size_t)part * NQ
                       + (((size_t)(bb * NH + h) * SEQ) + s) * DH + d0;
            *(float4*)dst = v;
        }
    }
}

// ---------------------------------------------------------------------------
// Out-projection GEMM: wmma 3-stage (proven, unchanged).
// ---------------------------------------------------------------------------
#define WAS_PITCH 36
#define WBS_PITCH 132
#define WSTAGE_F  (128*WAS_PITCH + 32*WBS_PITCH)
#define WGEMM_SMEM (3*WSTAGE_F*4)   // 105984 B

__global__ __launch_bounds__(256, 2)
void gemm_wmma_kernel(const float* __restrict__ B,
                      const float* __restrict__ bias, float* __restrict__ C,
                      int M, int N, int K)
{
    extern __shared__ float sm[];
    float* Cs = sm;

    const float* Abase = (const float*)g_attn;

    const int tid  = threadIdx.x;
    const int warp = tid >> 5;
    const int wr   = warp >> 1;
    const int wc   = warp & 1;
    const int rowBlock = blockIdx.y * 128;
    const int colBlock = blockIdx.x * 128;

    const int aRow0 = tid >> 3;
    const int aCol  = (tid & 7) * 4;
    const int bRow0 = tid >> 5;
    const int bCol  = (tid & 31) * 4;

    const float* Asrc = Abase + (size_t)(rowBlock + aRow0) * K + aCol;
    const float* Bsrc = B + (size_t)bRow0 * N + colBlock + bCol;

    const uint32_t smBase = smem_u32(sm);
    const uint32_t aOffB  = (uint32_t)((aRow0 * WAS_PITCH + aCol) * 4);
    const uint32_t bOffB  = (uint32_t)((128 * WAS_PITCH + bRow0 * WBS_PITCH + bCol) * 4);

    wmma::fragment<wmma::accumulator, 16, 16, 8, float> acc[2][4];
    #pragma unroll
    for (int i = 0; i < 2; i++)
        #pragma unroll
        for (int j = 0; j < 4; j++)
            wmma::fill_fragment(acc[i][j], 0.0f);

    const int NIT = K >> 5;

    auto issue = [&](int tt, int s) {
        const int k0 = tt << 5;
        const uint32_t sb = smBase + (uint32_t)s * (WSTAGE_F * 4);
        #pragma unroll
        for (int it = 0; it < 4; it++)
            CP_ASYNC16(sb + aOffB + (uint32_t)(it * 32 * WAS_PITCH * 4),
                       Asrc + (size_t)(it * 32) * K + k0);
        #pragma unroll
        for (int it = 0; it < 4; it++)
            CP_ASYNC16(sb + bOffB + (uint32_t)(it * 8 * WBS_PITCH * 4),
                       Bsrc + (size_t)(k0 + it * 8) * N);
        CP_COMMIT();
    };

    issue(0, 0);

    for (int t = 0; t < NIT; t++) {
        if (t + 1 < NIT) {
            issue(t + 1, (t + 1) % 3);
            CP_WAIT(1);
        } else {
            CP_WAIT(0);
        }
        __syncthreads();

        const float* As = sm + (t % 3) * WSTAGE_F;
        const float* Bs = As + 128 * WAS_PITCH;
        #pragma unroll
        for (int ks = 0; ks < 4; ks++) {
            wmma::fragment<wmma::matrix_a, 16, 16, 8, wmma::precision::tf32, wmma::row_major> af[2];
            wmma::fragment<wmma::matrix_b, 16, 16, 8, wmma::precision::tf32, wmma::row_major> bf[4];
            #pragma unroll
            for (int i = 0; i < 2; i++)
                wmma::load_matrix_sync(af[i], &As[(wr * 32 + i * 16) * WAS_PITCH + ks * 8], WAS_PITCH);
            #pragma unroll
            for (int j = 0; j < 4; j++)
                wmma::load_matrix_sync(bf[j], &Bs[(ks * 8) * WBS_PITCH + wc * 64 + j * 16], WBS_PITCH);
            #pragma unroll
            for (int i = 0; i < 2; i++)
                #pragma unroll
                for (int j = 0; j < 4; j++)
                    wmma::mma_sync(acc[i][j], af[i], bf[j], acc[i][j]);
        }
    }
    __syncthreads();

    #pragma unroll
    for (int i = 0; i < 2; i++)
        #pragma unroll
        for (int j = 0; j < 4; j++)
            wmma::store_matrix_sync(&Cs[(wr * 32 + i * 16) * CS_PITCH + wc * 64 + j * 16],
                                    acc[i][j], CS_PITCH, wmma::mem_row_major);
    __syncthreads();

    #pragma unroll
    for (int it = 0; it < 16; it++) {
        int u = tid + it * 256;
        int row = u >> 5, c4 = (u & 31) * 4;
        float4 v = *(float4*)&Cs[row * CS_PITCH + c4];
        const int gcol = colBlock + c4;
        v.x += bias[gcol + 0]; v.y += bias[gcol + 1];
        v.z += bias[gcol + 2]; v.w += bias[gcol + 3];
        const int gr = rowBlock + row;
        *(float4*)(C + (size_t)gr * N + gcol) = v;
    }
}

// ---------------------------------------------------------------------------
// Causal flash attention v6: 128-q tile, 512 threads, 2-stage KV ring,
// Q in registers, ldmatrix feeds for K, P, AND V (V stored d-major in gmem).
// smem stage: K[64][132] (8448) + Vt[128][68] (8704) = 17152 floats.
// ---------------------------------------------------------------------------
#define FP 132
#define VP 68
#define SP 68
#define KVSTRIDE (8448 + 8704)                     // 17152 floats per stage
#define FLASH_SMEM ((2*KVSTRIDE + 128*SP + 3*128) * 4)   // 173568 B

__global__ __launch_bounds__(512)
void flash_kernel()
{
    extern __shared__ float smf[];
    float* Ss   = smf + 2 * KVSTRIDE;
    float* mrow = Ss + 128 * SP;
    float* lrow = mrow + 128;
    float* arow = lrow + 128;

    const int qt = (int)(gridDim.x - 1) - (int)blockIdx.x;   // big tiles first
    const int h = blockIdx.y, b = blockIdx.z;
    const int bh = b * NH + h;

    const float* Qp = g_qkv + 0 * NQ + ((size_t)bh * SEQ + qt * 128) * DH;
    const float* Kp = g_qkv + 1 * NQ + (size_t)bh * SEQ * DH;
    const float* Vp = g_qkv + 2 * NQ + (size_t)bh * DH * SEQ;  // [d][s]

    const int tid  = threadIdx.x;
    const int warp = tid >> 5, lane = tid & 31;
    const int wr = warp >> 1, wc = warp & 1;      // wr 0..7, wc 0..1
    const int g  = lane >> 2, tq = lane & 3;
    const int sr = wr * 16;

    const float scale = 0.08838834764831845f;

    // ldmatrix lane offsets
    const uint32_t kOff0 = (uint32_t)(((wc * 32 + (lane & 7) + ((lane >> 4) << 3)) * FP
                                      + ((lane >> 3) & 1) * 4) * 4);
    const uint32_t kOff1 = kOff0 + (uint32_t)(16 * FP * 4);
    const uint32_t pOff  = (uint32_t)(((sr + (lane & 15)) * SP + (lane >> 4) * 4) * 4);
    uint32_t vOff[4];    // V B-fragment: pair p covers d-tiles 2p,2p+1
    #pragma unroll
    for (int p = 0; p < 4; p++)
        vOff[p] = (uint32_t)(((wc * 64 + p * 16 + (lane & 7) + ((lane >> 4) << 3)) * VP
                             + ((lane >> 3) & 1) * 4) * 4);
    const uint32_t ssB = smem_u32(Ss);

    auto issueKV = [&](int kt, int s) {
        const float* Kt = Kp + (size_t)kt * 64 * DH;
        const float* Vt = Vp + (size_t)kt * 64;       // column offset in [d][s]
        float* Kd = smf + s * KVSTRIDE;
        float* Vd = Kd + 8448;
        #pragma unroll
        for (int it = 0; it < 4; it++) {
            int u = tid + it * 512;
            int r = u >> 5, c = (u & 31) * 4;         // K: 64 rows x 32 chunks
            CP_ASYNC16(smem_u32(&Kd[r * FP + c]), Kt + r * DH + c);
            int vr = u >> 4, vc = (u & 15) * 4;       // V: 128 rows x 16 chunks
            CP_ASYNC16(smem_u32(&Vd[vr * VP + vc]), Vt + (size_t)vr * SEQ + vc);
        }
        CP_COMMIT();
    };

    issueKV(0, 0);
    // stage Q (128x128) into stage-1 region (17152 >= 128*132=16896)
    {
        float* Qtmp = smf + KVSTRIDE;
        #pragma unroll
        for (int it = 0; it < 8; it++) {
            int u = tid + it * 512;
            int r = u >> 5, c = (u & 31) * 4;
            *(float4*)&Qtmp[r * FP + c] = *(const float4*)(Qp + r * DH + c);
        }
    }
    if (tid < 128) { mrow[tid] = -1e30f; lrow[tid] = 0.f; }
    __syncthreads();

    uint32_t qf[16][4];
    {
        const float* Qtmp = smf + KVSTRIDE;
        #pragma unroll
        for (int ks = 0; ks < 16; ks++) {
            const int k0 = ks * 8;
            qf[ks][0] = __float_as_uint(Qtmp[(sr + g    ) * FP + k0 + tq    ]);
            qf[ks][1] = __float_as_uint(Qtmp[(sr + g + 8) * FP + k0 + tq    ]);
            qf[ks][2] = __float_as_uint(Qtmp[(sr + g    ) * FP + k0 + tq + 4]);
            qf[ks][3] = __float_as_uint(Qtmp[(sr + g + 8) * FP + k0 + tq + 4]);
        }
    }
    __syncthreads();   // qf read done before issueKV(1,1) overwrites stage 1

    float oc[8][4];
    #pragma unroll
    for (int t = 0; t < 8; t++)
        #pragma unroll
        for (int i = 0; i < 4; i++) oc[t][i] = 0.f;

    const int ktMax = 2 * qt + 1;
    for (int kt = 0; kt <= ktMax; kt++) {
        const int buf = kt & 1;
        const float* Ks = smf + buf * KVSTRIDE;

        if (kt < ktMax) {
            issueKV(kt + 1, buf ^ 1);
            CP_WAIT(1);
        } else {
            CP_WAIT(0);
        }
        __syncthreads();                     // [B] KV(kt) visible

        // ---- S = Q K^T : Q regs, K via ldmatrix ----
        {
            float sc[4][4] = {};
            const uint32_t kBase = smem_u32(Ks);
            #pragma unroll
            for (int ks = 0; ks < 16; ks++) {
                const uint32_t kb = (uint32_t)(ks * 32);
                uint32_t b0[4], b1[4];
                ldsm4(b0, kBase + kOff0 + kb);
                ldsm4(b1, kBase + kOff1 + kb);
                mma_tf32(sc[0], qf[ks], b0);
                mma_tf32(sc[1], qf[ks], b0 + 2);
                mma_tf32(sc[2], qf[ks], b1);
                mma_tf32(sc[3], qf[ks], b1 + 2);
            }
            const int sn0 = wc * 32;
            #pragma unroll
            for (int t = 0; t < 4; t++) {
                *(float2*)&Ss[(sr + g    ) * SP + sn0 + t * 8 + 2 * tq] =
                    make_float2(sc[t][0], sc[t][1]);
                *(float2*)&Ss[(sr + g + 8) * SP + sn0 + t * 8 + 2 * tq] =
                    make_float2(sc[t][2], sc[t][3]);
            }
        }
        __syncthreads();                     // [C]

        // ---- softmax (fp32): 4 lanes/row, 128 rows ----
        {
            const int row = tid >> 2;
            const int q4  = tid & 3;
            const int c0  = q4 * 16;
            const bool diag = (kt >= 2 * qt);
            const int qrow = qt * 128 + row;
            const int kc0  = kt * 64 + c0;
            float s[16];
            #pragma unroll
            for (int j = 0; j < 16; j++) {
                float v = Ss[row * SP + c0 + j] * scale;
                if (diag && (kc0 + j) > qrow) v = -1e30f;
                s[j] = v;
            }
            float mt = s[0];
            #pragma unroll
            for (int j = 1; j < 16; j++) mt = fmaxf(mt, s[j]);
            mt = fmaxf(mt, __shfl_xor_sync(0xffffffffu, mt, 1));
            mt = fmaxf(mt, __shfl_xor_sync(0xffffffffu, mt, 2));
            const float m_old = mrow[row];
            const float mnew  = fmaxf(m_old, mt);
            const float alpha = __expf(m_old - mnew);
            float rs = 0.f;
            #pragma unroll
            for (int j = 0; j < 16; j++) {
                float p = __expf(s[j] - mnew);
                rs += p;
                Ss[row * SP + c0 + j] = wmma::__float_to_tf32(p);
            }
            rs += __shfl_xor_sync(0xffffffffu, rs, 1);
            rs += __shfl_xor_sync(0xffffffffu, rs, 2);
            if (q4 == 0) {
                lrow[row] = lrow[row] * alpha + rs;
                mrow[row] = mnew;
                arow[row] = alpha;
            }
        }
        __syncthreads();                     // [D]

        // ---- O = O*alpha + P V : P and V both via ldmatrix ----
        {
            const float a_lo = arow[sr + g], a_hi = arow[sr + g + 8];
            #pragma unroll
            for (int t = 0; t < 8; t++) {
                oc[t][0] *= a_lo; oc[t][1] *= a_lo;
                oc[t][2] *= a_hi; oc[t][3] *= a_hi;
            }
            const uint32_t vBase = smem_u32(Ks + 8448);   // Vt region
            #pragma unroll
            for (int ks = 0; ks < 8; ks++) {
                const uint32_t kb = (uint32_t)(ks * 32);
                uint32_t a[4];
                ldsm4(a, ssB + pOff + kb);
                #pragma unroll
                for (int p = 0; p < 4; p++) {
                    uint32_t vb[4];
                    ldsm4(vb, vBase + vOff[p] + kb);
                    mma_tf32(oc[2*p  ], a, vb);
                    mma_tf32(oc[2*p+1], a, vb + 2);
                }
            }
        }
        __syncthreads();                     // [A] V reads done -> buf reusable
    }

    // epilogue: g_attn = tf32(O / l)
    {
        const int on0 = wc * 64;
        const float inv_lo = 1.0f / lrow[sr + g];
        const float inv_hi = 1.0f / lrow[sr + g + 8];
        float* Obase = g_attn + ((size_t)b * SEQ + qt * 128) * DM + h * DH;
        #pragma unroll
        for (int t = 0; t < 8; t++) {
            const int col = on0 + t * 8 + 2 * tq;
            float2 lo = make_float2(wmma::__float_to_tf32(oc[t][0] * inv_lo),
                                    wmma::__float_to_tf32(oc[t][1] * inv_lo));
            float2 hi = make_float2(wmma::__float_to_tf32(oc[t][2] * inv_hi),
                                    wmma::__float_to_tf32(oc[t][3] * inv_hi));
            *(float2*)(Obase + (size_t)(sr + g    ) * DM + col) = lo;
            *(float2*)(Obase + (size_t)(sr + g + 8) * DM + col) = hi;
        }
    }
}

// ---------------------------------------------------------------------------
extern "C" void kernel_launch(void* const* d_in, const int* in_sizes, int n_in,
                              void* d_out, int out_size)
{
    const float* x    = (const float*)d_in[0];
    const float* Wqkv = (const float*)d_in[1];
    const float* bqkv = (const float*)d_in[2];
    const float* Wout = (const float*)d_in[3];
    const float* bout = (const float*)d_in[4];
    float* out = (float*)d_out;

    const int M = BATCH * SEQ;

    cudaFuncSetAttribute(gemm_ldsm_kernel,
                         cudaFuncAttributeMaxDynamicSharedMemorySize, LGEMM_SMEM);
    cudaFuncSetAttribute(gemm_wmma_kernel,
                         cudaFuncAttributeMaxDynamicSharedMemorySize, WGEMM_SMEM);
    cudaFuncSetAttribute(flash_kernel,
                         cudaFuncAttributeMaxDynamicSharedMemorySize, FLASH_SMEM);

    float* xt; float* wq; float* wo;
    cudaGetSymbolAddress((void**)&xt, g_xt);
    cudaGetSymbolAddress((void**)&wq, g_wq);
    cudaGetSymbolAddress((void**)&wo, g_wo);

    // 0) pre-pass
    cvt_tf32_kernel<<<(int)((size_t)BATCH*SEQ*DM/4/256), 256>>>(x, xt, (int)((size_t)BATCH*SEQ*DM/4));
    {
        dim3 blk(32, 8);
        transpose_tf32_kernel<<<dim3((3*DM)/32, DM/32), blk>>>(Wqkv, wq, DM, 3*DM);
    }
    cvt_tf32_kernel<<<(int)((size_t)DM*DM/4/256), 256>>>(Wout, wo, (int)((size_t)DM*DM/4));

    // 1) QKV projection (ldmatrix + raw mma; V stored transposed)
    {
        dim3 grid((3 * DM) / 128, M / 128);
        gemm_ldsm_kernel<<<grid, 256, LGEMM_SMEM>>>(xt, wq, bqkv, M, 3 * DM, DM);
    }
    // 2) flash attention v6 (all-ldmatrix feeds)
    {
        dim3 grid(SEQ / 128, NH, BATCH);
        flash_kernel<<<grid, 512, FLASH_SMEM>>>();
    }
    // 3) output projection (wmma) -> d_out
    {
        dim3 grid(DM / 128, M / 128);
        gemm_wmma_kernel<<<grid, 256, WGEMM_SMEM>>>(wo, bout, out, M, DM, DM);
    }
}

// round 13
// speedup vs baseline: 3.3079x; 2.3406x over previous
#include <cuda_runtime.h>
#include <cuda_fp16.h>
#include <mma.h>
#include <math.h>
#include <stdint.h>

using namespace nvcuda;

#define BATCH 2
#define SEQ   2048
#define NH    16
#define DH    128
#define DM    2048
#define NQ    ((size_t)BATCH*NH*SEQ*DH)

// g_qkv: part 0 (Q), 1 (K): [b,h,s,d]; part 2 (V): [b,h,d,s] (transposed). fp16.
__device__ __half g_qkv[3*(size_t)BATCH*NH*SEQ*DH];
__device__ __half g_attn[(size_t)BATCH*SEQ*DM];
__device__ __half g_xt[(size_t)BATCH*SEQ*DM];
__device__ __half g_wq[(size_t)DM*3*DM];   // W_qkv^T [6144][2048]
__device__ __half g_wo[(size_t)DM*DM];     // W_out   [2048][2048] row-major

// ---------------------------------------------------------------------------
__device__ __forceinline__ uint32_t smem_u32(const void* p) {
    return (uint32_t)__cvta_generic_to_shared(p);
}
#define CP_ASYNC16(dst_u32, src_ptr) \
    asm volatile("cp.async.cg.shared.global [%0], [%1], 16;" :: "r"(dst_u32), "l"(src_ptr))
#define CP_COMMIT()   asm volatile("cp.async.commit_group;")
#define CP_WAIT(n)    asm volatile("cp.async.wait_group %0;" :: "n"(n))

// m16n8k16 fp16 mma, fp32 accum, D += A*B
__device__ __forceinline__ void mma_f16(float* d, const uint32_t* a, const uint32_t* b) {
    asm volatile(
        "mma.sync.aligned.m16n8k16.row.col.f32.f16.f16.f32 "
        "{%0,%1,%2,%3},{%4,%5,%6,%7},{%8,%9},{%0,%1,%2,%3};"
        : "+f"(d[0]), "+f"(d[1]), "+f"(d[2]), "+f"(d[3])
        : "r"(a[0]), "r"(a[1]), "r"(a[2]), "r"(a[3]), "r"(b[0]), "r"(b[1]));
}

__device__ __forceinline__ void ldsm4(uint32_t* r, uint32_t addr) {
    asm volatile("ldmatrix.sync.aligned.m8n8.x4.shared.b16 {%0,%1,%2,%3}, [%4];"
        : "=r"(r[0]), "=r"(r[1]), "=r"(r[2]), "=r"(r[3]) : "r"(addr));
}

// ---------------------------------------------------------------------------
// pre-passes: fp32 -> fp16
// ---------------------------------------------------------------------------
__global__ void cvt_f2h_kernel(const float* __restrict__ in,
                               __half* __restrict__ out, int n4)
{
    int i = blockIdx.x * blockDim.x + threadIdx.x;
    if (i < n4) {
        float4 v = ((const float4*)in)[i];
        __half2* o = (__half2*)(out + (size_t)i * 4);
        o[0] = __floats2half2_rn(v.x, v.y);
        o[1] = __floats2half2_rn(v.z, v.w);
    }
}

// in [R][C] fp32 -> out [C][R] fp16
__global__ void transpose_f2h_kernel(const float* __restrict__ in,
                                     __half* __restrict__ out, int R, int C)
{
    __shared__ float t[32][33];
    const int c0 = blockIdx.x * 32, r0 = blockIdx.y * 32;
    #pragma unroll
    for (int i = 0; i < 32; i += 8)
        t[threadIdx.y + i][threadIdx.x] =
            in[(size_t)(r0 + threadIdx.y + i) * C + c0 + threadIdx.x];
    __syncthreads();
    #pragma unroll
    for (int i = 0; i < 32; i += 8)
        out[(size_t)(c0 + threadIdx.y + i) * R + r0 + threadIdx.x] =
            __float2half(t[threadIdx.x][threadIdx.y + i]);
}

// ---------------------------------------------------------------------------
// QKV GEMM fp16: raw m16n8k16 + ldmatrix, BK=64 halfs, 3-stage cp.async.
// C = A[M,K] @ Bt[N,K]^T + bias -> scatter to g_qkv (Q/K normal, V transposed)
// ---------------------------------------------------------------------------
#define GP 72                         // smem pitch in halfs (64 + 8)
#define LA_BYTES (128*GP*2)           // 18432 B
#define LSTAGE_B (2*LA_BYTES)         // 36864 B
#define CS_PITCH 132
#define LGEMM_SMEM (3*LSTAGE_B)       // 110592 B

__global__ __launch_bounds__(256, 2)
void gemm_ldsm_kernel(const __half* __restrict__ Aglob, const __half* __restrict__ Bt,
                      const float* __restrict__ bias,
                      int M, int N, int K)
{
    extern __shared__ char smc[];
    float* Cs = (float*)smc;

    const int tid  = threadIdx.x;
    const int warp = tid >> 5, lane = tid & 31;
    const int wr   = warp >> 1;
    const int wc   = warp & 1;
    const int g    = lane >> 2, tq = lane & 3;
    const int rowBlock = blockIdx.y * 128;
    const int colBlock = blockIdx.x * 128;

    // loads: thread -> row tid>>3 (+32/it), 16B chunk tid&7
    const int ldRow = tid >> 3;
    const int ldCh  = tid & 7;
    const __half* Asrc = Aglob + (size_t)(rowBlock + ldRow) * K + ldCh * 8;
    const __half* Bsrc = Bt + (size_t)(colBlock + ldRow) * K + ldCh * 8;

    const uint32_t smBase = smem_u32(smc);
    const uint32_t ldOff  = (uint32_t)((ldRow * GP + ldCh * 8) * 2);

    uint32_t aOff[2];
    #pragma unroll
    for (int mi = 0; mi < 2; mi++)
        aOff[mi] = (uint32_t)(((wr * 32 + mi * 16 + (lane & 15)) * GP + (lane >> 4) * 8) * 2);
    uint32_t bOff[4];
    #pragma unroll
    for (int p = 0; p < 4; p++)
        bOff[p] = (uint32_t)(LA_BYTES +
                  ((wc * 64 + p * 16 + (lane & 7) + ((lane >> 4) << 3)) * GP
                   + ((lane >> 3) & 1) * 8) * 2);

    float acc[2][8][4] = {};
    const int NIT = K >> 6;   // BK=64

    auto issue = [&](int tt, int s) {
        const int k0 = tt << 6;
        const uint32_t sb = smBase + (uint32_t)s * LSTAGE_B;
        #pragma unroll
        for (int i = 0; i < 4; i++)
            CP_ASYNC16(sb + ldOff + (uint32_t)(i * 32 * GP * 2),
                       Asrc + (size_t)(i * 32) * K + k0);
        #pragma unroll
        for (int i = 0; i < 4; i++)
            CP_ASYNC16(sb + (uint32_t)LA_BYTES + ldOff + (uint32_t)(i * 32 * GP * 2),
                       Bsrc + (size_t)(i * 32) * K + k0);
        CP_COMMIT();
    };

    issue(0, 0);

    for (int t = 0; t < NIT; t++) {
        if (t + 1 < NIT) {
            issue(t + 1, (t + 1) % 3);
            CP_WAIT(1);
        } else {
            CP_WAIT(0);
        }
        __syncthreads();

        const uint32_t sb = smBase + (uint32_t)(t % 3) * LSTAGE_B;
        #pragma unroll
        for (int ks = 0; ks < 4; ks++) {
            const uint32_t kb = (uint32_t)(ks * 32);   // 16 halfs per k-step
            uint32_t a0[4], a1[4];
            ldsm4(a0, sb + aOff[0] + kb);
            ldsm4(a1, sb + aOff[1] + kb);
            #pragma unroll
            for (int p = 0; p < 4; p++) {
                uint32_t bb[4];
                ldsm4(bb, sb + bOff[p] + kb);
                mma_f16(acc[0][2*p  ], a0, bb);
                mma_f16(acc[0][2*p+1], a0, bb + 2);
                mma_f16(acc[1][2*p  ], a1, bb);
                mma_f16(acc[1][2*p+1], a1, bb + 2);
            }
        }
    }
    __syncthreads();

    #pragma unroll
    for (int mi = 0; mi < 2; mi++) {
        const int r_lo = wr * 32 + mi * 16 + g;
        #pragma unroll
        for (int j = 0; j < 8; j++) {
            const int col = wc * 64 + j * 8 + 2 * tq;
            *(float2*)&Cs[r_lo * CS_PITCH + col] =
                make_float2(acc[mi][j][0], acc[mi][j][1]);
            *(float2*)&Cs[(r_lo + 8) * CS_PITCH + col] =
                make_float2(acc[mi][j][2], acc[mi][j][3]);
        }
    }
    __syncthreads();

    #pragma unroll
    for (int it = 0; it < 16; it++) {
        int u = tid + it * 256;
        int row = u >> 5, c4 = (u & 31) * 4;
        float4 v = *(float4*)&Cs[row * CS_PITCH + c4];
        const int gcol = colBlock + c4;
        v.x += bias[gcol + 0]; v.y += bias[gcol + 1];
        v.z += bias[gcol + 2]; v.w += bias[gcol + 3];
        const int gr = rowBlock + row;
        const int part = gcol >> 11;
        const int c2   = gcol & 2047;
        const int h    = c2 >> 7;
        const int d0   = c2 & 127;
        const int bb   = gr >> 11;
        const int s    = gr & 2047;
        if (part == 2) {
            __half* dstv = g_qkv + 2 * NQ
                         + (((size_t)(bb * NH + h)) * DH + d0) * SEQ + s;
            dstv[0 * SEQ] = __float2half(v.x);
            dstv[1 * SEQ] = __float2half(v.y);
            dstv[2 * SEQ] = __float2half(v.z);
            dstv[3 * SEQ] = __float2half(v.w);
        } else {
            __half* dst = g_qkv + (size_t)part * NQ
                        + (((size_t)(bb * NH + h) * SEQ) + s) * DH + d0;
            __half2* d2 = (__half2*)dst;
            d2[0] = __floats2half2_rn(v.x, v.y);
            d2[1] = __floats2half2_rn(v.z, v.w);
        }
    }
}

// ---------------------------------------------------------------------------
// Out-projection GEMM fp16 wmma 3-stage: C = g_attn[M,K] @ B[K,N] + bias (fp32 out)
// ---------------------------------------------------------------------------
#define WAP 72
#define WBP 136
#define WA_BYTES (128*WAP*2)              // 18432
#define WSTAGE_B (WA_BYTES + 64*WBP*2)    // 35840
#define WGEMM_SMEM (3*WSTAGE_B)           // 107520 B

__global__ __launch_bounds__(256, 2)
void gemm_wmma_kernel(const __half* __restrict__ B,
                      const float* __restrict__ bias, float* __restrict__ C,
                      int M, int N, int K)
{
    extern __shared__ char smc[];
    float* Cs = (float*)smc;

    const __half* Abase = (const __half*)g_attn;

    const int tid  = threadIdx.x;
    const int warp = tid >> 5;
    const int wr   = warp >> 1;
    const int wc   = warp & 1;
    const int rowBlock = blockIdx.y * 128;
    const int colBlock = blockIdx.x * 128;

    // A: 128 rows x 8 chunks (16B) ; B: 64 rows x 16 chunks
    const int aRow = tid >> 3, aCh = tid & 7;
    const int bRow = tid >> 4, bCh = tid & 15;
    const __half* Asrc = Abase + (size_t)(rowBlock + aRow) * K + aCh * 8;
    const __half* Bsrc = B + (size_t)bRow * N + colBlock + bCh * 8;

    const uint32_t smBase = smem_u32(smc);
    const uint32_t aOffB  = (uint32_t)((aRow * WAP + aCh * 8) * 2);
    const uint32_t bOffB  = (uint32_t)(WA_BYTES + (bRow * WBP + bCh * 8) * 2);

    wmma::fragment<wmma::accumulator, 16, 16, 16, float> acc[2][4];
    #pragma unroll
    for (int i = 0; i < 2; i++)
        #pragma unroll
        for (int j = 0; j < 4; j++)
            wmma::fill_fragment(acc[i][j], 0.0f);

    const int NIT = K >> 6;

    auto issue = [&](int tt, int s) {
        const int k0 = tt << 6;
        const uint32_t sb = smBase + (uint32_t)s * WSTAGE_B;
        #pragma unroll
        for (int it = 0; it < 4; it++)
            CP_ASYNC16(sb + aOffB + (uint32_t)(it * 32 * WAP * 2),
                       Asrc + (size_t)(it * 32) * K + k0);
        #pragma unroll
        for (int it = 0; it < 4; it++)
            CP_ASYNC16(sb + bOffB + (uint32_t)(it * 16 * WBP * 2),
                       Bsrc + (size_t)(k0 + it * 16) * N);
        CP_COMMIT();
    };

    issue(0, 0);

    for (int t = 0; t < NIT; t++) {
        if (t + 1 < NIT) {
            issue(t + 1, (t + 1) % 3);
            CP_WAIT(1);
        } else {
            CP_WAIT(0);
        }
        __syncthreads();

        const __half* As = (const __half*)(smc + (t % 3) * WSTAGE_B);
        const __half* Bs = (const __half*)(smc + (t % 3) * WSTAGE_B + WA_BYTES);
        #pragma unroll
        for (int ks = 0; ks < 4; ks++) {
            wmma::fragment<wmma::matrix_a, 16, 16, 16, half, wmma::row_major> af[2];
            wmma::fragment<wmma::matrix_b, 16, 16, 16, half, wmma::row_major> bf[4];
            #pragma unroll
            for (int i = 0; i < 2; i++)
                wmma::load_matrix_sync(af[i], &As[(wr * 32 + i * 16) * WAP + ks * 16], WAP);
            #pragma unroll
            for (int j = 0; j < 4; j++)
                wmma::load_matrix_sync(bf[j], &Bs[(ks * 16) * WBP + wc * 64 + j * 16], WBP);
            #pragma unroll
            for (int i = 0; i < 2; i++)
                #pragma unroll
                for (int j = 0; j < 4; j++)
                    wmma::mma_sync(acc[i][j], af[i], bf[j], acc[i][j]);
        }
    }
    __syncthreads();

    #pragma unroll
    for (int i = 0; i < 2; i++)
        #pragma unroll
        for (int j = 0; j < 4; j++)
            wmma::store_matrix_sync(&Cs[(wr * 32 + i * 16) * CS_PITCH + wc * 64 + j * 16],
                                    acc[i][j], CS_PITCH, wmma::mem_row_major);
    __syncthreads();

    #pragma unroll
    for (int it = 0; it < 16; it++) {
        int u = tid + it * 256;
        int row = u >> 5, c4 = (u & 31) * 4;
        float4 v = *(float4*)&Cs[row * CS_PITCH + c4];
        const int gcol = colBlock + c4;
        v.x += bias[gcol + 0]; v.y += bias[gcol + 1];
        v.z += bias[gcol + 2]; v.w += bias[gcol + 3];
        const int gr = rowBlock + row;
        *(float4*)(C + (size_t)gr * N + gcol) = v;
    }
}

// ---------------------------------------------------------------------------
// Causal flash attention v7 (fp16): 128-q tile, 512 threads, 2-stage KV ring.
// Q/P/K/V all via ldmatrix (fp16-native). Softmax fp32.
// smem: stage s: K[64][136]h + Vt[128][72]h (35840 B each, 2 stages),
//       Ss fp32 [128][68], Ps half [128][72], stats 3x128 f32. Total 126464 B.
// ---------------------------------------------------------------------------
#define FPH 136
#define VPH 72
#define SPF 68
#define PPH 72
#define KVS_B (64*FPH*2 + 128*VPH*2)       // 35840 B per stage
#define FLASH_SMEM (2*KVS_B + 128*SPF*4 + 128*PPH*2 + 3*128*4)   // 126464 B

__global__ __launch_bounds__(512)
void flash_kernel()
{
    extern __shared__ char smc[];
    float* Ss   = (float*)(smc + 2 * KVS_B);
    __half* Ps  = (__half*)(smc + 2 * KVS_B + 128 * SPF * 4);
    float* mrow = (float*)(smc + 2 * KVS_B + 128 * SPF * 4 + 128 * PPH * 2);
    float* lrow = mrow + 128;
    float* arow = lrow + 128;

    const int qt = (int)(gridDim.x - 1) - (int)blockIdx.x;
    const int h = blockIdx.y, b = blockIdx.z;
    const int bh = b * NH + h;

    const __half* Qp = g_qkv + 0 * NQ + ((size_t)bh * SEQ + qt * 128) * DH;
    const __half* Kp = g_qkv + 1 * NQ + (size_t)bh * SEQ * DH;
    const __half* Vp = g_qkv + 2 * NQ + (size_t)bh * DH * SEQ;   // [d][s]

    const int tid  = threadIdx.x;
    const int warp = tid >> 5, lane = tid & 31;
    const int wr = warp >> 1, wc = warp & 1;
    const int g  = lane >> 2, tq = lane & 3;
    const int sr = wr * 16;

    const float scale = 0.08838834764831845f;

    // ldmatrix lane byte-offsets
    const uint32_t qOff  = (uint32_t)(((sr + (lane & 15)) * FPH + (lane >> 4) * 8) * 2);
    const uint32_t kOff0 = (uint32_t)(((wc * 32 + (lane & 7) + ((lane >> 4) << 3)) * FPH
                                      + ((lane >> 3) & 1) * 8) * 2);
    const uint32_t kOff1 = kOff0 + (uint32_t)(16 * FPH * 2);
    const uint32_t pOff  = (uint32_t)(((sr + (lane & 15)) * PPH + (lane >> 4) * 8) * 2);
    uint32_t vOff[4];
    #pragma unroll
    for (int p = 0; p < 4; p++)
        vOff[p] = (uint32_t)(((wc * 64 + p * 16 + (lane & 7) + ((lane >> 4) << 3)) * VPH
                             + ((lane >> 3) & 1) * 8) * 2);
    const uint32_t psB = smem_u32(Ps);

    auto issueKV = [&](int kt, int s) {
        const __half* Kt = Kp + (size_t)kt * 64 * DH;
        const __half* Vt = Vp + (size_t)kt * 64;
        const uint32_t kB = smem_u32(smc + s * KVS_B);
        const uint32_t vB = kB + (uint32_t)(64 * FPH * 2);
        #pragma unroll
        for (int it = 0; it < 2; it++) {
            int u = tid + it * 512;
            int kr = u >> 4, kc = u & 15;                 // K: 64 x 16 chunks
            CP_ASYNC16(kB + (uint32_t)((kr * FPH + kc * 8) * 2), Kt + kr * DH + kc * 8);
            int vr = u >> 3, vc = u & 7;                  // V: 128 x 8 chunks
            CP_ASYNC16(vB + (uint32_t)((vr * VPH + vc * 8) * 2), Vt + (size_t)vr * SEQ + vc * 8);
        }
        CP_COMMIT();
    };

    issueKV(0, 0);
    // stage Q (128x128 halfs) into stage-1 region (128*136*2=34816 <= 35840)
    {
        __half* Qtmp = (__half*)(smc + KVS_B);
        #pragma unroll
        for (int it = 0; it < 4; it++) {
            int u = tid + it * 512;
            int r = u >> 4, c = u & 15;
            *(uint4*)&Qtmp[r * FPH + c * 8] = *(const uint4*)(Qp + r * DH + c * 8);
        }
    }
    if (tid < 128) { mrow[tid] = -1e30f; lrow[tid] = 0.f; }
    __syncthreads();

    uint32_t qf[8][4];
    {
        const uint32_t qB = smem_u32(smc + KVS_B);
        #pragma unroll
        for (int ks = 0; ks < 8; ks++)
            ldsm4(qf[ks], qB + qOff + (uint32_t)(ks * 32));
    }
    __syncthreads();   // qf done before issueKV(1,1) overwrites stage 1

    float oc[8][4];
    #pragma unroll
    for (int t = 0; t < 8; t++)
        #pragma unroll
        for (int i = 0; i < 4; i++) oc[t][i] = 0.f;

    const int ktMax = 2 * qt + 1;
    for (int kt = 0; kt <= ktMax; kt++) {
        const int buf = kt & 1;
        const uint32_t kBase = smem_u32(smc + buf * KVS_B);
        const uint32_t vBase = kBase + (uint32_t)(64 * FPH * 2);

        if (kt < ktMax) {
            issueKV(kt + 1, buf ^ 1);
            CP_WAIT(1);
        } else {
            CP_WAIT(0);
        }
        __syncthreads();                     // KV(kt) visible

        // ---- S = Q K^T ----
        {
            float sc[4][4] = {};
            #pragma unroll
            for (int ks = 0; ks < 8; ks++) {
                const uint32_t kb = (uint32_t)(ks * 32);
                uint32_t b0[4], b1[4];
                ldsm4(b0, kBase + kOff0 + kb);
                ldsm4(b1, kBase + kOff1 + kb);
                mma_f16(sc[0], qf[ks], b0);
                mma_f16(sc[1], qf[ks], b0 + 2);
                mma_f16(sc[2], qf[ks], b1);
                mma_f16(sc[3], qf[ks], b1 + 2);
            }
            const int sn0 = wc * 32;
            #pragma unroll
            for (int t = 0; t < 4; t++) {
                *(float2*)&Ss[(sr + g    ) * SPF + sn0 + t * 8 + 2 * tq] =
                    make_float2(sc[t][0], sc[t][1]);
                *(float2*)&Ss[(sr + g + 8) * SPF + sn0 + t * 8 + 2 * tq] =
                    make_float2(sc[t][2], sc[t][3]);
            }
        }
        __syncthreads();

        // ---- softmax fp32; P -> half ----
        {
            const int row = tid >> 2;
            const int q4  = tid & 3;
            const int c0  = q4 * 16;
            const bool diag = (kt >= 2 * qt);
            const int qrow = qt * 128 + row;
            const int kc0  = kt * 64 + c0;
            float s[16];
            #pragma unroll
            for (int j = 0; j < 16; j++) {
                float v = Ss[row * SPF + c0 + j] * scale;
                if (diag && (kc0 + j) > qrow) v = -1e30f;
                s[j] = v;
            }
            float mt = s[0];
            #pragma unroll
            for (int j = 1; j < 16; j++) mt = fmaxf(mt, s[j]);
            mt = fmaxf(mt, __shfl_xor_sync(0xffffffffu, mt, 1));
            mt = fmaxf(mt, __shfl_xor_sync(0xffffffffu, mt, 2));
            const float m_old = mrow[row];
            const float mnew  = fmaxf(m_old, mt);
            const float alpha = __expf(m_old - mnew);
            float p[16], rs = 0.f;
            #pragma unroll
            for (int j = 0; j < 16; j++) {
                p[j] = __expf(s[j] - mnew);
                rs += p[j];
            }
            #pragma unroll
            for (int j = 0; j < 8; j++)
                *(__half2*)&Ps[row * PPH + c0 + 2 * j] =
                    __floats2half2_rn(p[2 * j], p[2 * j + 1]);
            rs += __shfl_xor_sync(0xffffffffu, rs, 1);
            rs += __shfl_xor_sync(0xffffffffu, rs, 2);
            if (q4 == 0) {
                lrow[row] = lrow[row] * alpha + rs;
                mrow[row] = mnew;
                arow[row] = alpha;
            }
        }
        __syncthreads();

        // ---- O = O*alpha + P V ----
        {
            const float a_lo = arow[sr + g], a_hi = arow[sr + g + 8];
            #pragma unroll
            for (int t = 0; t < 8; t++) {
                oc[t][0] *= a_lo; oc[t][1] *= a_lo;
                oc[t][2] *= a_hi; oc[t][3] *= a_hi;
            }
            #pragma unroll
            for (int ks = 0; ks < 4; ks++) {
                const uint32_t kb = (uint32_t)(ks * 32);
                uint32_t a[4];
                ldsm4(a, psB + pOff + kb);
                #pragma unroll
                for (int p = 0; p < 4; p++) {
                    uint32_t vb[4];
                    ldsm4(vb, vBase + vOff[p] + kb);
                    mma_f16(oc[2*p  ], a, vb);
                    mma_f16(oc[2*p+1], a, vb + 2);
                }
            }
        }
        __syncthreads();                     // V reads done -> buf reusable
    }

    // epilogue: g_attn = half(O / l)
    {
        const int on0 = wc * 64;
        const float inv_lo = 1.0f / lrow[sr + g];
        const float inv_hi = 1.0f / lrow[sr + g + 8];
        __half* Obase = g_attn + ((size_t)b * SEQ + qt * 128) * DM + h * DH;
        #pragma unroll
        for (int t = 0; t < 8; t++) {
            const int col = on0 + t * 8 + 2 * tq;
            *(__half2*)(Obase + (size_t)(sr + g    ) * DM + col) =
                __floats2half2_rn(oc[t][0] * inv_lo, oc[t][1] * inv_lo);
            *(__half2*)(Obase + (size_t)(sr + g + 8) * DM + col) =
                __floats2half2_rn(oc[t][2] * inv_hi, oc[t][3] * inv_hi);
        }
    }
}

// ---------------------------------------------------------------------------
extern "C" void kernel_launch(void* const* d_in, const int* in_sizes, int n_in,
                              void* d_out, int out_size)
{
    const float* x    = (const float*)d_in[0];
    const float* Wqkv = (const float*)d_in[1];
    const float* bqkv = (const float*)d_in[2];
    const float* Wout = (const float*)d_in[3];
    const float* bout = (const float*)d_in[4];
    float* out = (float*)d_out;

    const int M = BATCH * SEQ;

    cudaFuncSetAttribute(gemm_ldsm_kernel,
                         cudaFuncAttributeMaxDynamicSharedMemorySize, LGEMM_SMEM);
    cudaFuncSetAttribute(gemm_wmma_kernel,
                         cudaFuncAttributeMaxDynamicSharedMemorySize, WGEMM_SMEM);
    cudaFuncSetAttribute(flash_kernel,
                         cudaFuncAttributeMaxDynamicSharedMemorySize, FLASH_SMEM);

    __half* xt; __half* wq; __half* wo;
    cudaGetSymbolAddress((void**)&xt, g_xt);
    cudaGetSymbolAddress((void**)&wq, g_wq);
    cudaGetSymbolAddress((void**)&wo, g_wo);

    // 0) pre-pass: x -> fp16; W_qkv -> fp16 transposed [N][K]; W_out -> fp16
    cvt_f2h_kernel<<<(int)((size_t)BATCH*SEQ*DM/4/256), 256>>>(x, xt, (int)((size_t)BATCH*SEQ*DM/4));
    {
        dim3 blk(32, 8);
        transpose_f2h_kernel<<<dim3((3*DM)/32, DM/32), blk>>>(Wqkv, wq, DM, 3*DM);
    }
    cvt_f2h_kernel<<<(int)((size_t)DM*DM/4/256), 256>>>(Wout, wo, (int)((size_t)DM*DM/4));

    // 1) QKV projection (fp16 mma + ldmatrix; V stored transposed)
    {
        dim3 grid((3 * DM) / 128, M / 128);
        gemm_ldsm_kernel<<<grid, 256, LGEMM_SMEM>>>(xt, wq, bqkv, M, 3 * DM, DM);
    }
    // 2) flash attention v7 (fp16)
    {
        dim3 grid(SEQ / 128, NH, BATCH);
        flash_kernel<<<grid, 512, FLASH_SMEM>>>();
    }
    // 3) output projection (fp16 wmma) -> d_out fp32
    {
        dim3 grid(DM / 128, M / 128);
        gemm_wmma_kernel<<<grid, 256, WGEMM_SMEM>>>(wo, bout, out, M, DM, DM);
    }
}

// round 14
// speedup vs baseline: 3.5626x; 1.0770x over previous
#include <cuda_runtime.h>
#include <cuda_fp16.h>
#include <mma.h>
#include <math.h>
#include <stdint.h>

using namespace nvcuda;

#define BATCH 2
#define SEQ   2048
#define NH    16
#define DH    128
#define DM    2048
#define NQ    ((size_t)BATCH*NH*SEQ*DH)
#define QSCALE 0.08838834764831845f

// g_qkv: part 0 (Q, pre-scaled by 1/sqrt(d)), 1 (K): [b,h,s,d]; part 2 (V): [b,h,d,s]
__device__ __half g_qkv[3*(size_t)BATCH*NH*SEQ*DH];
__device__ __half g_attn[(size_t)BATCH*SEQ*DM];
__device__ __half g_xt[(size_t)BATCH*SEQ*DM];
__device__ __half g_wq[(size_t)DM*3*DM];   // W_qkv^T [6144][2048]
__device__ __half g_wo[(size_t)DM*DM];     // W_out   [2048][2048] row-major

// ---------------------------------------------------------------------------
__device__ __forceinline__ uint32_t smem_u32(const void* p) {
    return (uint32_t)__cvta_generic_to_shared(p);
}
#define CP_ASYNC16(dst_u32, src_ptr) \
    asm volatile("cp.async.cg.shared.global [%0], [%1], 16;" :: "r"(dst_u32), "l"(src_ptr))
#define CP_COMMIT()   asm volatile("cp.async.commit_group;")
#define CP_WAIT(n)    asm volatile("cp.async.wait_group %0;" :: "n"(n))
#define BAR_PAIR(id)  asm volatile("bar.sync %0, 64;" :: "r"(id) : "memory")

__device__ __forceinline__ void mma_f16(float* d, const uint32_t* a, const uint32_t* b) {
    asm volatile(
        "mma.sync.aligned.m16n8k16.row.col.f32.f16.f16.f32 "
        "{%0,%1,%2,%3},{%4,%5,%6,%7},{%8,%9},{%0,%1,%2,%3};"
        : "+f"(d[0]), "+f"(d[1]), "+f"(d[2]), "+f"(d[3])
        : "r"(a[0]), "r"(a[1]), "r"(a[2]), "r"(a[3]), "r"(b[0]), "r"(b[1]));
}

__device__ __forceinline__ void ldsm4(uint32_t* r, uint32_t addr) {
    asm volatile("ldmatrix.sync.aligned.m8n8.x4.shared.b16 {%0,%1,%2,%3}, [%4];"
        : "=r"(r[0]), "=r"(r[1]), "=r"(r[2]), "=r"(r[3]) : "r"(addr));
}

// ---------------------------------------------------------------------------
// pre-passes: fp32 -> fp16
// ---------------------------------------------------------------------------
__global__ void cvt_f2h_kernel(const float* __restrict__ in,
                               __half* __restrict__ out, int n4)
{
    int i = blockIdx.x * blockDim.x + threadIdx.x;
    if (i < n4) {
        float4 v = ((const float4*)in)[i];
        __half2* o = (__half2*)(out + (size_t)i * 4);
        o[0] = __floats2half2_rn(v.x, v.y);
        o[1] = __floats2half2_rn(v.z, v.w);
    }
}

__global__ void transpose_f2h_kernel(const float* __restrict__ in,
                                     __half* __restrict__ out, int R, int C)
{
    __shared__ float t[32][33];
    const int c0 = blockIdx.x * 32, r0 = blockIdx.y * 32;
    #pragma unroll
    for (int i = 0; i < 32; i += 8)
        t[threadIdx.y + i][threadIdx.x] =
            in[(size_t)(r0 + threadIdx.y + i) * C + c0 + threadIdx.x];
    __syncthreads();
    #pragma unroll
    for (int i = 0; i < 32; i += 8)
        out[(size_t)(c0 + threadIdx.y + i) * R + r0 + threadIdx.x] =
            __float2half(t[threadIdx.x][threadIdx.y + i]);
}

// ---------------------------------------------------------------------------
// QKV GEMM fp16 (round-13 proven). Q part pre-scaled by 1/sqrt(d) at scatter.
// ---------------------------------------------------------------------------
#define GP 72
#define LA_BYTES (128*GP*2)
#define LSTAGE_B (2*LA_BYTES)
#define CS_PITCH 132
#define LGEMM_SMEM (3*LSTAGE_B)       // 110592 B

__global__ __launch_bounds__(256, 2)
void gemm_ldsm_kernel(const __half* __restrict__ Aglob, const __half* __restrict__ Bt,
                      const float* __restrict__ bias,
                      int M, int N, int K)
{
    extern __shared__ char smc[];
    float* Cs = (float*)smc;

    const int tid  = threadIdx.x;
    const int warp = tid >> 5, lane = tid & 31;
    const int wr   = warp >> 1;
    const int wc   = warp & 1;
    const int g    = lane >> 2, tq = lane & 3;
    const int rowBlock = blockIdx.y * 128;
    const int colBlock = blockIdx.x * 128;

    const int ldRow = tid >> 3;
    const int ldCh  = tid & 7;
    const __half* Asrc = Aglob + (size_t)(rowBlock + ldRow) * K + ldCh * 8;
    const __half* Bsrc = Bt + (size_t)(colBlock + ldRow) * K + ldCh * 8;

    const uint32_t smBase = smem_u32(smc);
    const uint32_t ldOff  = (uint32_t)((ldRow * GP + ldCh * 8) * 2);

    uint32_t aOff[2];
    #pragma unroll
    for (int mi = 0; mi < 2; mi++)
        aOff[mi] = (uint32_t)(((wr * 32 + mi * 16 + (lane & 15)) * GP + (lane >> 4) * 8) * 2);
    uint32_t bOff[4];
    #pragma unroll
    for (int p = 0; p < 4; p++)
        bOff[p] = (uint32_t)(LA_BYTES +
                  ((wc * 64 + p * 16 + (lane & 7) + ((lane >> 4) << 3)) * GP
                   + ((lane >> 3) & 1) * 8) * 2);

    float acc[2][8][4] = {};
    const int NIT = K >> 6;

    auto issue = [&](int tt, int s) {
        const int k0 = tt << 6;
        const uint32_t sb = smBase + (uint32_t)s * LSTAGE_B;
        #pragma unroll
        for (int i = 0; i < 4; i++)
            CP_ASYNC16(sb + ldOff + (uint32_t)(i * 32 * GP * 2),
                       Asrc + (size_t)(i * 32) * K + k0);
        #pragma unroll
        for (int i = 0; i < 4; i++)
            CP_ASYNC16(sb + (uint32_t)LA_BYTES + ldOff + (uint32_t)(i * 32 * GP * 2),
                       Bsrc + (size_t)(i * 32) * K + k0);
        CP_COMMIT();
    };

    issue(0, 0);

    for (int t = 0; t < NIT; t++) {
        if (t + 1 < NIT) {
            issue(t + 1, (t + 1) % 3);
            CP_WAIT(1);
        } else {
            CP_WAIT(0);
        }
        __syncthreads();

        const uint32_t sb = smBase + (uint32_t)(t % 3) * LSTAGE_B;
        #pragma unroll
        for (int ks = 0; ks < 4; ks++) {
            const uint32_t kb = (uint32_t)(ks * 32);
            uint32_t a0[4], a1[4];
            ldsm4(a0, sb + aOff[0] + kb);
            ldsm4(a1, sb + aOff[1] + kb);
            #pragma unroll
            for (int p = 0; p < 4; p++) {
                uint32_t bb[4];
                ldsm4(bb, sb + bOff[p] + kb);
                mma_f16(acc[0][2*p  ], a0, bb);
                mma_f16(acc[0][2*p+1], a0, bb + 2);
                mma_f16(acc[1][2*p  ], a1, bb);
                mma_f16(acc[1][2*p+1], a1, bb + 2);
            }
        }
    }
    __syncthreads();

    #pragma unroll
    for (int mi = 0; mi < 2; mi++) {
        const int r_lo = wr * 32 + mi * 16 + g;
        #pragma unroll
        for (int j = 0; j < 8; j++) {
            const int col = wc * 64 + j * 8 + 2 * tq;
            *(float2*)&Cs[r_lo * CS_PITCH + col] =
                make_float2(acc[mi][j][0], acc[mi][j][1]);
            *(float2*)&Cs[(r_lo + 8) * CS_PITCH + col] =
                make_float2(acc[mi][j][2], acc[mi][j][3]);
        }
    }
    __syncthreads();

    #pragma unroll
    for (int it = 0; it < 16; it++) {
        int u = tid + it * 256;
        int row = u >> 5, c4 = (u & 31) * 4;
        float4 v = *(float4*)&Cs[row * CS_PITCH + c4];
        const int gcol = colBlock + c4;
        v.x += bias[gcol + 0]; v.y += bias[gcol + 1];
        v.z += bias[gcol + 2]; v.w += bias[gcol + 3];
        const int gr = rowBlock + row;
        const int part = gcol >> 11;
        const int c2   = gcol & 2047;
        const int h    = c2 >> 7;
        const int d0   = c2 & 127;
        const int bb   = gr >> 11;
        const int s    = gr & 2047;
        if (part == 2) {
            __half* dstv = g_qkv + 2 * NQ
                         + (((size_t)(bb * NH + h)) * DH + d0) * SEQ + s;
            dstv[0 * SEQ] = __float2half(v.x);
            dstv[1 * SEQ] = __float2half(v.y);
            dstv[2 * SEQ] = __float2half(v.z);
            dstv[3 * SEQ] = __float2half(v.w);
        } else {
            if (part == 0) {   // pre-scale Q by 1/sqrt(d)
                v.x *= QSCALE; v.y *= QSCALE; v.z *= QSCALE; v.w *= QSCALE;
            }
            __half* dst = g_qkv + (size_t)part * NQ
                        + (((size_t)(bb * NH + h) * SEQ) + s) * DH + d0;
            __half2* d2 = (__half2*)dst;
            d2[0] = __floats2half2_rn(v.x, v.y);
            d2[1] = __floats2half2_rn(v.z, v.w);
        }
    }
}

// ---------------------------------------------------------------------------
// Out-projection GEMM fp16 wmma 3-stage (round-13 proven, unchanged).
// ---------------------------------------------------------------------------
#define WAP 72
#define WBP 136
#define WA_BYTES (128*WAP*2)
#define WSTAGE_B (WA_BYTES + 64*WBP*2)
#define WGEMM_SMEM (3*WSTAGE_B)           // 107520 B

__global__ __launch_bounds__(256, 2)
void gemm_wmma_kernel(const __half* __restrict__ B,
                      const float* __restrict__ bias, float* __restrict__ C,
                      int M, int N, int K)
{
    extern __shared__ char smc[];
    float* Cs = (float*)smc;

    const __half* Abase = (const __half*)g_attn;

    const int tid  = threadIdx.x;
    const int warp = tid >> 5;
    const int wr   = warp >> 1;
    const int wc   = warp & 1;
    const int rowBlock = blockIdx.y * 128;
    const int colBlock = blockIdx.x * 128;

    const int aRow = tid >> 3, aCh = tid & 7;
    const int bRow = tid >> 4, bCh = tid & 15;
    const __half* Asrc = Abase + (size_t)(rowBlock + aRow) * K + aCh * 8;
    const __half* Bsrc = B + (size_t)bRow * N + colBlock + bCh * 8;

    const uint32_t smBase = smem_u32(smc);
    const uint32_t aOffB  = (uint32_t)((aRow * WAP + aCh * 8) * 2);
    const uint32_t bOffB  = (uint32_t)(WA_BYTES + (bRow * WBP + bCh * 8) * 2);

    wmma::fragment<wmma::accumulator, 16, 16, 16, float> acc[2][4];
    #pragma unroll
    for (int i = 0; i < 2; i++)
        #pragma unroll
        for (int j = 0; j < 4; j++)
            wmma::fill_fragment(acc[i][j], 0.0f);

    const int NIT = K >> 6;

    auto issue = [&](int tt, int s) {
        const int k0 = tt << 6;
        const uint32_t sb = smBase + (uint32_t)s * WSTAGE_B;
        #pragma unroll
        for (int it = 0; it < 4; it++)
            CP_ASYNC16(sb + aOffB + (uint32_t)(it * 32 * WAP * 2),
                       Asrc + (size_t)(it * 32) * K + k0);
        #pragma unroll
        for (int it = 0; it < 4; it++)
            CP_ASYNC16(sb + bOffB + (uint32_t)(it * 16 * WBP * 2),
                       Bsrc + (size_t)(k0 + it * 16) * N);
        CP_COMMIT();
    };

    issue(0, 0);

    for (int t = 0; t < NIT; t++) {
        if (t + 1 < NIT) {
            issue(t + 1, (t + 1) % 3);
            CP_WAIT(1);
        } else {
            CP_WAIT(0);
        }
        __syncthreads();

        const __half* As = (const __half*)(smc + (t % 3) * WSTAGE_B);
        const __half* Bs = (const __half*)(smc + (t % 3) * WSTAGE_B + WA_BYTES);
        #pragma unroll
        for (int ks = 0; ks < 4; ks++) {
            wmma::fragment<wmma::matrix_a, 16, 16, 16, half, wmma::row_major> af[2];
            wmma::fragment<wmma::matrix_b, 16, 16, 16, half, wmma::row_major> bf[4];
            #pragma unroll
            for (int i = 0; i < 2; i++)
                wmma::load_matrix_sync(af[i], &As[(wr * 32 + i * 16) * WAP + ks * 16], WAP);
            #pragma unroll
            for (int j = 0; j < 4; j++)
                wmma::load_matrix_sync(bf[j], &Bs[(ks * 16) * WBP + wc * 64 + j * 16], WBP);
            #pragma unroll
            for (int i = 0; i < 2; i++)
                #pragma unroll
                for (int j = 0; j < 4; j++)
                    wmma::mma_sync(acc[i][j], af[i], bf[j], acc[i][j]);
        }
    }
    __syncthreads();

    #pragma unroll
    for (int i = 0; i < 2; i++)
        #pragma unroll
        for (int j = 0; j < 4; j++)
            wmma::store_matrix_sync(&Cs[(wr * 32 + i * 16) * CS_PITCH + wc * 64 + j * 16],
                                    acc[i][j], CS_PITCH, wmma::mem_row_major);
    __syncthreads();

    #pragma unroll
    for (int it = 0; it < 16; it++) {
        int u = tid + it * 256;
        int row = u >> 5, c4 = (u & 31) * 4;
        float4 v = *(float4*)&Cs[row * CS_PITCH + c4];
        const int gcol = colBlock + c4;
        v.x += bias[gcol + 0]; v.y += bias[gcol + 1];
        v.z += bias[gcol + 2]; v.w += bias[gcol + 3];
        const int gr = rowBlock + row;
        *(float4*)(C + (size_t)gr * N + gcol) = v;
    }
}

// ---------------------------------------------------------------------------
// Causal flash attention v8 (fp16): in-register softmax, pair-local barriers.
// 128-q tile, 512 threads, 2-stage KV ring, all operands via ldmatrix.
// smem: 2 KV stages (35840 B each) + Ps half[128][72] + stats[128][2] fp32.
// Row state (m, l) lives in registers (replicated across quad lanes).
// ---------------------------------------------------------------------------
#define FPH 136
#define VPH 72
#define PPH 72
#define KVS_B (64*FPH*2 + 128*VPH*2)       // 35840 B
#define FLASH_SMEM (2*KVS_B + 128*PPH*2 + 256*4)   // 91136 B

__global__ __launch_bounds__(512)
void flash_kernel()
{
    extern __shared__ char smc[];
    __half* Ps  = (__half*)(smc + 2 * KVS_B);
    float* xbuf = (float*)(smc + 2 * KVS_B + 128 * PPH * 2);   // [128][2]

    const int qt = (int)(gridDim.x - 1) - (int)blockIdx.x;
    const int h = blockIdx.y, b = blockIdx.z;
    const int bh = b * NH + h;

    const __half* Qp = g_qkv + 0 * NQ + ((size_t)bh * SEQ + qt * 128) * DH;
    const __half* Kp = g_qkv + 1 * NQ + (size_t)bh * SEQ * DH;
    const __half* Vp = g_qkv + 2 * NQ + (size_t)bh * DH * SEQ;

    const int tid  = threadIdx.x;
    const int warp = tid >> 5, lane = tid & 31;
    const int wr = warp >> 1, wc = warp & 1;
    const int g  = lane >> 2, tq = lane & 3;
    const int sr = wr * 16;
    const int sn0 = wc * 32;
    const int barid = wr + 1;

    // ldmatrix lane byte-offsets
    const uint32_t qOff  = (uint32_t)(((sr + (lane & 15)) * FPH + (lane >> 4) * 8) * 2);
    const uint32_t kOff0 = (uint32_t)(((wc * 32 + (lane & 7) + ((lane >> 4) << 3)) * FPH
                                      + ((lane >> 3) & 1) * 8) * 2);
    const uint32_t kOff1 = kOff0 + (uint32_t)(16 * FPH * 2);
    const uint32_t pOff  = (uint32_t)(((sr + (lane & 15)) * PPH + (lane >> 4) * 8) * 2);
    uint32_t vOff[4];
    #pragma unroll
    for (int p = 0; p < 4; p++)
        vOff[p] = (uint32_t)(((wc * 64 + p * 16 + (lane & 7) + ((lane >> 4) << 3)) * VPH
                             + ((lane >> 3) & 1) * 8) * 2);
    const uint32_t psB = smem_u32(Ps);

    auto issueKV = [&](int kt, int s) {
        const __half* Kt = Kp + (size_t)kt * 64 * DH;
        const __half* Vt = Vp + (size_t)kt * 64;
        const uint32_t kB = smem_u32(smc + s * KVS_B);
        const uint32_t vB = kB + (uint32_t)(64 * FPH * 2);
        #pragma unroll
        for (int it = 0; it < 2; it++) {
            int u = tid + it * 512;
            int kr = u >> 4, kc = u & 15;
            CP_ASYNC16(kB + (uint32_t)((kr * FPH + kc * 8) * 2), Kt + kr * DH + kc * 8);
            int vr = u >> 3, vc = u & 7;
            CP_ASYNC16(vB + (uint32_t)((vr * VPH + vc * 8) * 2), Vt + (size_t)vr * SEQ + vc * 8);
        }
        CP_COMMIT();
    };

    issueKV(0, 0);
    {
        __half* Qtmp = (__half*)(smc + KVS_B);
        #pragma unroll
        for (int it = 0; it < 4; it++) {
            int u = tid + it * 512;
            int r = u >> 4, c = u & 15;
            *(uint4*)&Qtmp[r * FPH + c * 8] = *(const uint4*)(Qp + r * DH + c * 8);
        }
    }
    __syncthreads();

    uint32_t qf[8][4];
    {
        const uint32_t qB = smem_u32(smc + KVS_B);
        #pragma unroll
        for (int ks = 0; ks < 8; ks++)
            ldsm4(qf[ks], qB + qOff + (uint32_t)(ks * 32));
    }
    __syncthreads();   // qf done before issueKV(1,1) overwrites stage 1

    float oc[8][4];
    #pragma unroll
    for (int t = 0; t < 8; t++)
        #pragma unroll
        for (int i = 0; i < 4; i++) oc[t][i] = 0.f;

    float m_reg[2] = {-1e30f, -1e30f};
    float l_reg[2] = {0.f, 0.f};

    const int ktMax = 2 * qt + 1;
    for (int kt = 0; kt <= ktMax; kt++) {
        const int buf = kt & 1;
        const uint32_t kBase = smem_u32(smc + buf * KVS_B);
        const uint32_t vBase = kBase + (uint32_t)(64 * FPH * 2);

        if (kt < ktMax) {
            issueKV(kt + 1, buf ^ 1);
            CP_WAIT(1);
        } else {
            CP_WAIT(0);
        }
        __syncthreads();                     // [B] KV(kt) visible

        // ---- S = Q K^T (Q pre-scaled) ----
        float sc[4][4] = {};
        #pragma unroll
        for (int ks = 0; ks < 8; ks++) {
            const uint32_t kb = (uint32_t)(ks * 32);
            uint32_t b0[4], b1[4];
            ldsm4(b0, kBase + kOff0 + kb);
            ldsm4(b1, kBase + kOff1 + kb);
            mma_f16(sc[0], qf[ks], b0);
            mma_f16(sc[1], qf[ks], b0 + 2);
            mma_f16(sc[2], qf[ks], b1);
            mma_f16(sc[3], qf[ks], b1 + 2);
        }

        // ---- causal mask (in regs) ----
        if (kt >= 2 * qt) {
            const int rlo = qt * 128 + sr + g;
            #pragma unroll
            for (int t = 0; t < 4; t++) {
                const int c0 = kt * 64 + sn0 + t * 8 + 2 * tq;
                if (c0     > rlo    ) sc[t][0] = -1e30f;
                if (c0 + 1 > rlo    ) sc[t][1] = -1e30f;
                if (c0     > rlo + 8) sc[t][2] = -1e30f;
                if (c0 + 1 > rlo + 8) sc[t][3] = -1e30f;
            }
        }

        // ---- in-register softmax: row stats in regs, cross-warp via smem ----
        {
            float mx0 = fmaxf(fmaxf(sc[0][0], sc[0][1]), fmaxf(sc[1][0], sc[1][1]));
            mx0 = fmaxf(mx0, fmaxf(fmaxf(sc[2][0], sc[2][1]), fmaxf(sc[3][0], sc[3][1])));
            float mx1 = fmaxf(fmaxf(sc[0][2], sc[0][3]), fmaxf(sc[1][2], sc[1][3]));
            mx1 = fmaxf(mx1, fmaxf(fmaxf(sc[2][2], sc[2][3]), fmaxf(sc[3][2], sc[3][3])));
            mx0 = fmaxf(mx0, __shfl_xor_sync(0xffffffffu, mx0, 1));
            mx0 = fmaxf(mx0, __shfl_xor_sync(0xffffffffu, mx0, 2));
            mx1 = fmaxf(mx1, __shfl_xor_sync(0xffffffffu, mx1, 1));
            mx1 = fmaxf(mx1, __shfl_xor_sync(0xffffffffu, mx1, 2));
            if (tq == 0) {
                xbuf[(sr + g) * 2 + wc]     = mx0;
                xbuf[(sr + g + 8) * 2 + wc] = mx1;
            }
            BAR_PAIR(barid);                 // pair-local max exchange
            mx0 = fmaxf(mx0, xbuf[(sr + g) * 2 + (wc ^ 1)]);
            mx1 = fmaxf(mx1, xbuf[(sr + g + 8) * 2 + (wc ^ 1)]);

            const float mn0 = fmaxf(m_reg[0], mx0);
            const float mn1 = fmaxf(m_reg[1], mx1);
            const float a0 = __expf(m_reg[0] - mn0);
            const float a1 = __expf(m_reg[1] - mn1);
            m_reg[0] = mn0; m_reg[1] = mn1;

            float rs0 = 0.f, rs1 = 0.f;
            #pragma unroll
            for (int t = 0; t < 4; t++) {
                float p0 = __expf(sc[t][0] - mn0);
                float p1 = __expf(sc[t][1] - mn0);
                float p2 = __expf(sc[t][2] - mn1);
                float p3 = __expf(sc[t][3] - mn1);
                rs0 += p0 + p1;
                rs1 += p2 + p3;
                const int col = sn0 + t * 8 + 2 * tq;
                *(__half2*)&Ps[(sr + g    ) * PPH + col] = __floats2half2_rn(p0, p1);
                *(__half2*)&Ps[(sr + g + 8) * PPH + col] = __floats2half2_rn(p2, p3);
            }
            rs0 += __shfl_xor_sync(0xffffffffu, rs0, 1);
            rs0 += __shfl_xor_sync(0xffffffffu, rs0, 2);
            rs1 += __shfl_xor_sync(0xffffffffu, rs1, 1);
            rs1 += __shfl_xor_sync(0xffffffffu, rs1, 2);
            l_reg[0] = l_reg[0] * a0 + rs0;
            l_reg[1] = l_reg[1] * a1 + rs1;

            #pragma unroll
            for (int t = 0; t < 8; t++) {
                oc[t][0] *= a0; oc[t][1] *= a0;
                oc[t][2] *= a1; oc[t][3] *= a1;
            }
        }
        BAR_PAIR(barid);                     // P (both halves) visible to pair

        // ---- O += P V ----
        #pragma unroll
        for (int ks = 0; ks < 4; ks++) {
            const uint32_t kb = (uint32_t)(ks * 32);
            uint32_t a[4];
            ldsm4(a, psB + pOff + kb);
            #pragma unroll
            for (int p = 0; p < 4; p++) {
                uint32_t vb[4];
                ldsm4(vb, vBase + vOff[p] + kb);
                mma_f16(oc[2*p  ], a, vb);
                mma_f16(oc[2*p+1], a, vb + 2);
            }
        }
        __syncthreads();                     // [A] buf reusable; P safe to rewrite
    }

    // ---- epilogue: merge l across warp pair, write O/l ----
    if (tq == 0) {
        xbuf[(sr + g) * 2 + wc]     = l_reg[0];
        xbuf[(sr + g + 8) * 2 + wc] = l_reg[1];
    }
    __syncthreads();
    {
        const float inv_lo = 1.0f / (xbuf[(sr + g) * 2] + xbuf[(sr + g) * 2 + 1]);
        const float inv_hi = 1.0f / (xbuf[(sr + g + 8) * 2] + xbuf[(sr + g + 8) * 2 + 1]);
        const int on0 = wc * 64;
        __half* Obase = g_attn + ((size_t)b * SEQ + qt * 128) * DM + h * DH;
        #pragma unroll
        for (int t = 0; t < 8; t++) {
            const int col = on0 + t * 8 + 2 * tq;
            *(__half2*)(Obase + (size_t)(sr + g    ) * DM + col) =
                __floats2half2_rn(oc[t][0] * inv_lo, oc[t][1] * inv_lo);
            *(__half2*)(Obase + (size_t)(sr + g + 8) * DM + col) =
                __floats2half2_rn(oc[t][2] * inv_hi, oc[t][3] * inv_hi);
        }
    }
}

// ---------------------------------------------------------------------------
extern "C" void kernel_launch(void* const* d_in, const int* in_sizes, int n_in,
                              void* d_out, int out_size)
{
    const float* x    = (const float*)d_in[0];
    const float* Wqkv = (const float*)d_in[1];
    const float* bqkv = (const float*)d_in[2];
    const float* Wout = (const float*)d_in[3];
    const float* bout = (const float*)d_in[4];
    float* out = (float*)d_out;

    const int M = BATCH * SEQ;

    cudaFuncSetAttribute(gemm_ldsm_kernel,
                         cudaFuncAttributeMaxDynamicSharedMemorySize, LGEMM_SMEM);
    cudaFuncSetAttribute(gemm_wmma_kernel,
                         cudaFuncAttributeMaxDynamicSharedMemorySize, WGEMM_SMEM);
    cudaFuncSetAttribute(flash_kernel,
                         cudaFuncAttributeMaxDynamicSharedMemorySize, FLASH_SMEM);

    __half* xt; __half* wq; __half* wo;
    cudaGetSymbolAddress((void**)&xt, g_xt);
    cudaGetSymbolAddress((void**)&wq, g_wq);
    cudaGetSymbolAddress((void**)&wo, g_wo);

    // 0) pre-pass
    cvt_f2h_kernel<<<(int)((size_t)BATCH*SEQ*DM/4/256), 256>>>(x, xt, (int)((size_t)BATCH*SEQ*DM/4));
    {
        dim3 blk(32, 8);
        transpose_f2h_kernel<<<dim3((3*DM)/32, DM/32), blk>>>(Wqkv, wq, DM, 3*DM);
    }
    cvt_f2h_kernel<<<(int)((size_t)DM*DM/4/256), 256>>>(Wout, wo, (int)((size_t)DM*DM/4));

    // 1) QKV projection (fp16 mma + ldmatrix; Q pre-scaled, V transposed)
    {
        dim3 grid((3 * DM) / 128, M / 128);
        gemm_ldsm_kernel<<<grid, 256, LGEMM_SMEM>>>(xt, wq, bqkv, M, 3 * DM, DM);
    }
    // 2) flash attention v8 (in-register softmax)
    {
        dim3 grid(SEQ / 128, NH, BATCH);
        flash_kernel<<<grid, 512, FLASH_SMEM>>>();
    }
    // 3) output projection (fp16 wmma) -> d_out fp32
    {
        dim3 grid(DM / 128, M / 128);
        gemm_wmma_kernel<<<grid, 256, WGEMM_SMEM>>>(wo, bout, out, M, DM, DM);
    }
}